// round 1
// baseline (speedup 1.0000x reference)
#include <cuda_runtime.h>

// ---------------- problem constants ----------------
constexpr int B    = 8;
constexpr int L    = 512;
constexpr int HID  = 1024;
constexpr int H    = 16;
constexpr int HD   = 64;     // head dim
constexpr int TAB  = 129;    // 2*64+1 relative-position table rows
constexpr int BL   = B * L;  // 4096

// ---------------- device scratch (no runtime allocs allowed) ----------------
__device__ float g_Q[BL * HID];                 // 16.8 MB
__device__ float g_K[BL * HID];
__device__ float g_V[BL * HID];
__device__ float g_P[BL * H * TAB];             // 33.8 MB  P[b,q,h,t] = q4·table_k[t]
__device__ float g_attn[(size_t)B * H * L * L]; // 134 MB   attn[b,h,q,k]
__device__ float g_X[BL * HID];                 // w1+w2 merged, [B,L,HID]

// =====================================================================
// Generic C[M,N] = A[M,K] @ W[N,K]^T (+ bias). M%128==0, K%8==0, N guarded.
// 128x128 tile, BK=8, 256 threads, 8x8 per thread.
// =====================================================================
__global__ __launch_bounds__(256) void sgemm_atb(
    const float* __restrict__ A, const float* __restrict__ W,
    const float* __restrict__ bias, float* __restrict__ C,
    int M, int N, int K)
{
    __shared__ float As[8][128];
    __shared__ float Bs[8][128];

    const int tid = threadIdx.x;
    const int m0  = blockIdx.y * 128;
    const int n0  = blockIdx.x * 128;
    const int tx  = tid & 15;
    const int ty  = tid >> 4;
    const int lrow = tid >> 1;
    const int lcol = (tid & 1) << 2;

    const float* Ap = A + (size_t)(m0 + lrow) * K + lcol;
    const bool  wok = (n0 + lrow) < N;
    const float* Wp = W + (size_t)(n0 + lrow) * K + lcol;

    float acc[8][8];
#pragma unroll
    for (int i = 0; i < 8; i++)
#pragma unroll
        for (int j = 0; j < 8; j++) acc[i][j] = 0.f;

    for (int k0 = 0; k0 < K; k0 += 8) {
        float4 av = *reinterpret_cast<const float4*>(Ap + k0);
        float4 wv = wok ? *reinterpret_cast<const float4*>(Wp + k0)
                        : make_float4(0.f, 0.f, 0.f, 0.f);
        As[lcol + 0][lrow] = av.x; As[lcol + 1][lrow] = av.y;
        As[lcol + 2][lrow] = av.z; As[lcol + 3][lrow] = av.w;
        Bs[lcol + 0][lrow] = wv.x; Bs[lcol + 1][lrow] = wv.y;
        Bs[lcol + 2][lrow] = wv.z; Bs[lcol + 3][lrow] = wv.w;
        __syncthreads();
#pragma unroll
        for (int kk = 0; kk < 8; kk++) {
            float a[8], bb[8];
            *reinterpret_cast<float4*>(&a[0])  = *reinterpret_cast<const float4*>(&As[kk][ty * 8]);
            *reinterpret_cast<float4*>(&a[4])  = *reinterpret_cast<const float4*>(&As[kk][ty * 8 + 4]);
            *reinterpret_cast<float4*>(&bb[0]) = *reinterpret_cast<const float4*>(&Bs[kk][tx * 8]);
            *reinterpret_cast<float4*>(&bb[4]) = *reinterpret_cast<const float4*>(&Bs[kk][tx * 8 + 4]);
#pragma unroll
            for (int i = 0; i < 8; i++)
#pragma unroll
                for (int j = 0; j < 8; j++) acc[i][j] += a[i] * bb[j];
        }
        __syncthreads();
    }

#pragma unroll
    for (int i = 0; i < 8; i++) {
        const int m = m0 + ty * 8 + i;
        float* Crow = C + (size_t)m * N;
#pragma unroll
        for (int j = 0; j < 8; j++) {
            const int n = n0 + tx * 8 + j;
            if (n < N) Crow[n] = acc[i][j] + (bias ? bias[n] : 0.f);
        }
    }
}

// =====================================================================
// Kernel 3: fused scores + relative-position gather + softmax
// block = (q-tile of 32, h, b); 256 threads; writes g_attn[b,h,q,k]
// =====================================================================
// dynamic shared layout (in floats)
constexpr int SQT_STRIDE = 36;   // sQt[d][q], padded
constexpr int SK_STRIDE  = 68;   // sK[k][d], padded
constexpr int SP_STRIDE  = 132;  // sP[q][t], padded
constexpr int SS_STRIDE  = 516;  // sS[q][k], padded
constexpr int SM3_QT = 0;
constexpr int SM3_K  = SM3_QT + 64 * SQT_STRIDE;
constexpr int SM3_P  = SM3_K  + 64 * SK_STRIDE;
constexpr int SM3_S  = SM3_P  + 32 * SP_STRIDE;
constexpr int SM3_F  = SM3_S  + 32 * SS_STRIDE;         // ints live here
constexpr int SM3_TOTAL = SM3_F + 32 * SS_STRIDE;
constexpr size_t SM3_BYTES = (size_t)SM3_TOTAL * 4;     // ~171.5 KB

__global__ __launch_bounds__(256) void scores_softmax_kernel(const int* __restrict__ fm)
{
    extern __shared__ float smem[];
    float* sQt = smem + SM3_QT;
    float* sK  = smem + SM3_K;
    float* sP  = smem + SM3_P;
    float* sS  = smem + SM3_S;
    int*   sF  = reinterpret_cast<int*>(smem + SM3_F);

    const int tid = threadIdx.x;
    const int q0  = blockIdx.x * 32;
    const int h   = blockIdx.y;
    const int b   = blockIdx.z;

    // --- load Q tile (transposed to [d][q]) ---
    {
        const int q = tid >> 3;
        const int dbase = (tid & 7) * 8;
        const float* src = g_Q + (size_t)(b * L + q0 + q) * HID + h * HD + dbase;
        float4 v0 = *reinterpret_cast<const float4*>(src);
        float4 v1 = *reinterpret_cast<const float4*>(src + 4);
        sQt[(dbase + 0) * SQT_STRIDE + q] = v0.x;
        sQt[(dbase + 1) * SQT_STRIDE + q] = v0.y;
        sQt[(dbase + 2) * SQT_STRIDE + q] = v0.z;
        sQt[(dbase + 3) * SQT_STRIDE + q] = v0.w;
        sQt[(dbase + 4) * SQT_STRIDE + q] = v1.x;
        sQt[(dbase + 5) * SQT_STRIDE + q] = v1.y;
        sQt[(dbase + 6) * SQT_STRIDE + q] = v1.z;
        sQt[(dbase + 7) * SQT_STRIDE + q] = v1.w;
    }
    // --- load P tile ---
    for (int i = tid; i < 32 * TAB; i += 256) {
        const int q = i / TAB, t = i - q * TAB;
        sP[q * SP_STRIDE + t] = g_P[((size_t)(b * L + q0 + q) * H + h) * TAB + t];
    }
    // --- load final_mat tile ---
    {
        const int* src = fm + (size_t)(b * L + q0) * L;
        for (int i = tid; i < 32 * L; i += 256) {
            const int q = i >> 9, k = i & 511;
            sF[q * SS_STRIDE + k] = src[i];
        }
    }

    const int kl = tid >> 2;  // 0..63 local k
    const int qg = tid & 3;   // q group (8 q's each)

    for (int kt = 0; kt < 8; kt++) {
        __syncthreads();  // protect sK (and initial loads on kt==0)
        {
            const int krow = tid >> 2;
            const int dseg = (tid & 3) * 16;
            const float* src = g_K + (size_t)(b * L + kt * 64 + krow) * HID + h * HD + dseg;
            float* dst = sK + krow * SK_STRIDE + dseg;
#pragma unroll
            for (int j = 0; j < 4; j++)
                *reinterpret_cast<float4*>(dst + 4 * j) =
                    *reinterpret_cast<const float4*>(src + 4 * j);
        }
        __syncthreads();

        float acc[8];
#pragma unroll
        for (int i = 0; i < 8; i++) acc[i] = 0.f;
        const float* krow = sK + kl * SK_STRIDE;
#pragma unroll 8
        for (int d = 0; d < 64; d++) {
            const float kv = krow[d];
            const float* qr = sQt + d * SQT_STRIDE + qg * 8;
            float4 a0 = *reinterpret_cast<const float4*>(qr);
            float4 a1 = *reinterpret_cast<const float4*>(qr + 4);
            acc[0] += a0.x * kv; acc[1] += a0.y * kv;
            acc[2] += a0.z * kv; acc[3] += a0.w * kv;
            acc[4] += a1.x * kv; acc[5] += a1.y * kv;
            acc[6] += a1.z * kv; acc[7] += a1.w * kv;
        }
        const int kglob = kt * 64 + kl;
#pragma unroll
        for (int i = 0; i < 8; i++) {
            const int q = qg * 8 + i;
            const int t = sF[q * SS_STRIDE + kglob];
            sS[q * SS_STRIDE + kglob] = (acc[i] + sP[q * SP_STRIDE + t]) * 0.125f;
        }
    }
    __syncthreads();

    // --- softmax: warp w handles rows 4w..4w+3 ---
    const int lane = tid & 31;
    const int warp = tid >> 5;
    for (int r = warp * 4; r < warp * 4 + 4; r++) {
        float* row = sS + r * SS_STRIDE;
        float m = -1e30f;
#pragma unroll
        for (int i = 0; i < 16; i++) m = fmaxf(m, row[lane + 32 * i]);
#pragma unroll
        for (int o = 16; o > 0; o >>= 1) m = fmaxf(m, __shfl_xor_sync(0xffffffffu, m, o));
        float s = 0.f;
#pragma unroll
        for (int i = 0; i < 16; i++) {
            const float e = __expf(row[lane + 32 * i] - m);
            row[lane + 32 * i] = e;
            s += e;
        }
#pragma unroll
        for (int o = 16; o > 0; o >>= 1) s += __shfl_xor_sync(0xffffffffu, s, o);
        const float inv = 1.f / s;
        float* dst = g_attn + ((size_t)(b * H + h) * L + (q0 + r)) * L;
#pragma unroll
        for (int i = 0; i < 16; i++) dst[lane + 32 * i] = row[lane + 32 * i] * inv;
    }
}

// =====================================================================
// Kernel 4: fused w1 = attn@V, bucket scatter S[t] += attn, w2 = S@table_v
// block = (q-tile of 32, h, b); writes g_X[b,q,h*64+d]
// =====================================================================
constexpr int SM4_A  = 0;                      // sA[q][k] 32x516
constexpr int SM4_V  = SM4_A  + 32 * 516;      // sV[k][d] 64x68
constexpr int SM4_SB = SM4_V  + 64 * 68;       // buckets 32x132
constexpr int SM4_TV = SM4_SB + 32 * 132;      // table_v 129x64
constexpr int SM4_TOTAL = SM4_TV + TAB * 64;
constexpr size_t SM4_BYTES = (size_t)SM4_TOTAL * 4;  // ~130 KB

__global__ __launch_bounds__(256) void w12_kernel(const int* __restrict__ fm,
                                                  const float* __restrict__ table_v)
{
    extern __shared__ float smem[];
    float* sA  = smem + SM4_A;
    float* sV  = smem + SM4_V;
    float* sSb = smem + SM4_SB;
    float* sTv = smem + SM4_TV;

    const int tid = threadIdx.x;
    const int q0  = blockIdx.x * 32;
    const int h   = blockIdx.y;
    const int b   = blockIdx.z;

    // --- load attn tile, table_v, zero buckets ---
    {
        const float* asrc = g_attn + ((size_t)(b * H + h) * L + q0) * L;
        for (int i = tid; i < 32 * 512; i += 256) {
            const int q = i >> 9, k = i & 511;
            sA[q * 516 + k] = asrc[i];
        }
    }
    for (int i = tid; i < TAB * 64; i += 256) sTv[i] = table_v[i];
    for (int i = tid; i < 32 * 132; i += 256) sSb[i] = 0.f;

    const int q  = tid >> 3;
    const int dg = tid & 7;

    float acc1[8];
#pragma unroll
    for (int i = 0; i < 8; i++) acc1[i] = 0.f;

    for (int kt = 0; kt < 8; kt++) {
        __syncthreads();
        {
            const int krow = tid >> 2;
            const int dseg = (tid & 3) * 16;
            const float* src = g_V + (size_t)(b * L + kt * 64 + krow) * HID + h * HD + dseg;
            float* dst = sV + krow * 68 + dseg;
#pragma unroll
            for (int j = 0; j < 4; j++)
                *reinterpret_cast<float4*>(dst + 4 * j) =
                    *reinterpret_cast<const float4*>(src + 4 * j);
        }
        __syncthreads();

        const float* arow = sA + q * 516 + kt * 64;
#pragma unroll 8
        for (int k = 0; k < 64; k++) {
            const float a = arow[k];
            const float* vr = sV + k * 68 + dg * 8;
            float4 v0 = *reinterpret_cast<const float4*>(vr);
            float4 v1 = *reinterpret_cast<const float4*>(vr + 4);
            acc1[0] += a * v0.x; acc1[1] += a * v0.y;
            acc1[2] += a * v0.z; acc1[3] += a * v0.w;
            acc1[4] += a * v1.x; acc1[5] += a * v1.y;
            acc1[6] += a * v1.z; acc1[7] += a * v1.w;
        }
    }

    // --- bucket scatter: thread (q, kg) handles k = 8i + kg ---
    {
        const int kg = tid & 7;
        const int* fr = fm + (size_t)(b * L + q0 + q) * L;
        const float* ar = sA + q * 516;
        for (int i = 0; i < 64; i++) {
            const int k = i * 8 + kg;
            const int t = fr[k];
            atomicAdd(&sSb[q * 132 + t], ar[k]);
        }
    }
    __syncthreads();

    // --- w2 = S @ table_v ---
    float acc2[8];
#pragma unroll
    for (int i = 0; i < 8; i++) acc2[i] = 0.f;
    const float* sbr = sSb + q * 132;
    for (int t = 0; t < TAB; t++) {
        const float s = sbr[t];
        const float* tvr = sTv + t * 64 + dg * 8;
        float4 v0 = *reinterpret_cast<const float4*>(tvr);
        float4 v1 = *reinterpret_cast<const float4*>(tvr + 4);
        acc2[0] += s * v0.x; acc2[1] += s * v0.y;
        acc2[2] += s * v0.z; acc2[3] += s * v0.w;
        acc2[4] += s * v1.x; acc2[5] += s * v1.y;
        acc2[6] += s * v1.z; acc2[7] += s * v1.w;
    }

    float* dst = g_X + (size_t)(b * L + q0 + q) * HID + h * HD + dg * 8;
    float4 o0 = make_float4(acc1[0] + acc2[0], acc1[1] + acc2[1],
                            acc1[2] + acc2[2], acc1[3] + acc2[3]);
    float4 o1 = make_float4(acc1[4] + acc2[4], acc1[5] + acc2[5],
                            acc1[6] + acc2[6], acc1[7] + acc2[7]);
    *reinterpret_cast<float4*>(dst)     = o0;
    *reinterpret_cast<float4*>(dst + 4) = o1;
}

// =====================================================================
// launch
// =====================================================================
extern "C" void kernel_launch(void* const* d_in, const int* in_sizes, int n_in,
                              void* d_out, int out_size)
{
    const float* query   = (const float*)d_in[0];
    const float* key     = (const float*)d_in[1];
    const float* value   = (const float*)d_in[2];
    const int*   fm      = (const int*)  d_in[3];
    const float* Wq      = (const float*)d_in[4];
    const float* bq      = (const float*)d_in[5];
    const float* Wk      = (const float*)d_in[6];
    const float* bk      = (const float*)d_in[7];
    const float* Wv      = (const float*)d_in[8];
    const float* bv      = (const float*)d_in[9];
    const float* Wo      = (const float*)d_in[10];
    const float* bo      = (const float*)d_in[11];
    const float* table_k = (const float*)d_in[12];
    const float* table_v = (const float*)d_in[13];
    float* out = (float*)d_out;

    cudaFuncSetAttribute(scores_softmax_kernel,
                         cudaFuncAttributeMaxDynamicSharedMemorySize, (int)SM3_BYTES);
    cudaFuncSetAttribute(w12_kernel,
                         cudaFuncAttributeMaxDynamicSharedMemorySize, (int)SM4_BYTES);

    float* gQ; cudaGetSymbolAddress((void**)&gQ, g_Q);
    float* gX; cudaGetSymbolAddress((void**)&gX, g_X);
    float* gP; cudaGetSymbolAddress((void**)&gP, g_P);
    float* gK; cudaGetSymbolAddress((void**)&gK, g_K);
    float* gV; cudaGetSymbolAddress((void**)&gV, g_V);

    const dim3 gproj(HID / 128, BL / 128);  // (8, 32)
    sgemm_atb<<<gproj, 256>>>(query, Wq, bq, gQ, BL, HID, HID);
    sgemm_atb<<<gproj, 256>>>(key,   Wk, bk, gK, BL, HID, HID);
    sgemm_atb<<<gproj, 256>>>(value, Wv, bv, gV, BL, HID, HID);

    // P[b,q,h,t] : [65536, 64] @ [129, 64]^T
    const dim3 gridP((TAB + 127) / 128, (BL * H) / 128);  // (2, 512)
    sgemm_atb<<<gridP, 256>>>(gQ, table_k, nullptr, gP, BL * H, TAB, HD);

    const dim3 gattn(L / 32, H, B);  // (16, 16, 8)
    scores_softmax_kernel<<<gattn, 256, SM3_BYTES>>>(fm);
    w12_kernel<<<gattn, 256, SM4_BYTES>>>(fm, table_v);

    sgemm_atb<<<gproj, 256>>>(gX, Wo, bo, out, BL, HID, HID);
}

// round 3
// speedup vs baseline: 1.3184x; 1.3184x over previous
#include <cuda_runtime.h>

// ---------------- problem constants ----------------
constexpr int B    = 8;
constexpr int L    = 512;
constexpr int HID  = 1024;
constexpr int H    = 16;
constexpr int HD   = 64;     // head dim
constexpr int TAB  = 129;    // 2*64+1 relative-position table rows
constexpr int BL   = B * L;  // 4096

// ---------------- device scratch (no runtime allocs allowed) ----------------
__device__ float g_Q[BL * HID];                 // 16.8 MB
__device__ float g_K[BL * HID];
__device__ float g_V[BL * HID];
__device__ float g_P[BL * H * TAB];             // 33.8 MB  P[b,q,h,t] = q4·table_k[t]
__device__ float g_attn[(size_t)B * H * L * L]; // 134 MB   attn[b,h,q,k]
__device__ float g_X[BL * HID];                 // w1+w2 merged, [B,L,HID]

// =====================================================================
// tf32 tensor-core GEMM: C[M,N] = A[M,K] @ W[N,K]^T (+bias)
// M%128==0, K%32==0, N guarded. 128x128x32 tile, 256 thr, 8 warps.
// Warp tile 64x32 = 4x4 m16n8k8 mma. cvt.rna.tf32 at smem-fill.
// =====================================================================
__device__ __forceinline__ float tf32r(float x) {
    unsigned y;
    asm("cvt.rna.tf32.f32 %0, %1;" : "=r"(y) : "f"(x));
    return __uint_as_float(y);
}

__device__ __forceinline__ void mma_tf32(float d[4], const float a[4], const float b[2]) {
    unsigned const* A = reinterpret_cast<unsigned const*>(a);
    unsigned const* Bp = reinterpret_cast<unsigned const*>(b);
    asm volatile(
        "mma.sync.aligned.m16n8k8.row.col.f32.tf32.tf32.f32 "
        "{%0,%1,%2,%3}, {%4,%5,%6,%7}, {%8,%9}, {%0,%1,%2,%3};"
        : "+f"(d[0]), "+f"(d[1]), "+f"(d[2]), "+f"(d[3])
        : "r"(A[0]), "r"(A[1]), "r"(A[2]), "r"(A[3]),
          "r"(Bp[0]), "r"(Bp[1]));
}

constexpr int SKS = 36;  // smem k-stride (pad 32 -> 36: conflict-free frags)

__global__ __launch_bounds__(256) void gemm_tf32(
    const float* __restrict__ A, const float* __restrict__ W,
    const float* __restrict__ bias, float* __restrict__ C,
    int M, int N, int K)
{
    __shared__ float As[128 * SKS];
    __shared__ float Bs[128 * SKS];

    const int tid  = threadIdx.x;
    const int m0   = blockIdx.y * 128;
    const int n0   = blockIdx.x * 128;
    const int lane = tid & 31;
    const int g    = lane >> 2;      // group id 0..7
    const int t    = lane & 3;       // thread in group
    const int warp = tid >> 5;
    const int wm   = warp & 1;       // 0..1  (64 rows each)
    const int wn   = warp >> 1;      // 0..3  (32 cols each)

    // global-load mapping: 2 threads per row, 16 floats each
    const int lrow = tid >> 1;            // 0..127
    const int lc   = (tid & 1) * 16;      // 0 or 16
    const float* Ap = A + (size_t)(m0 + lrow) * K + lc;
    const bool  wok = (n0 + lrow) < N;
    const float* Wp = W + (size_t)(n0 + lrow) * K + lc;

    float acc[4][4][4];
#pragma unroll
    for (int i = 0; i < 4; i++)
#pragma unroll
        for (int j = 0; j < 4; j++)
#pragma unroll
            for (int r = 0; r < 4; r++) acc[i][j][r] = 0.f;

    float4 ar[4], wr[4];
#pragma unroll
    for (int j = 0; j < 4; j++) {
        ar[j] = *reinterpret_cast<const float4*>(Ap + 4 * j);
        wr[j] = wok ? *reinterpret_cast<const float4*>(Wp + 4 * j)
                    : make_float4(0.f, 0.f, 0.f, 0.f);
    }

    for (int k0 = 0; k0 < K; k0 += 32) {
        // stage current tile (cvt to tf32 on the way in)
        float* asd = As + lrow * SKS + lc;
        float* bsd = Bs + lrow * SKS + lc;
#pragma unroll
        for (int j = 0; j < 4; j++) {
            float4 av = make_float4(tf32r(ar[j].x), tf32r(ar[j].y), tf32r(ar[j].z), tf32r(ar[j].w));
            float4 wv = make_float4(tf32r(wr[j].x), tf32r(wr[j].y), tf32r(wr[j].z), tf32r(wr[j].w));
            *reinterpret_cast<float4*>(asd + 4 * j) = av;
            *reinterpret_cast<float4*>(bsd + 4 * j) = wv;
        }
        __syncthreads();

        // prefetch next tile
        if (k0 + 32 < K) {
#pragma unroll
            for (int j = 0; j < 4; j++) {
                ar[j] = *reinterpret_cast<const float4*>(Ap + k0 + 32 + 4 * j);
                wr[j] = wok ? *reinterpret_cast<const float4*>(Wp + k0 + 32 + 4 * j)
                            : make_float4(0.f, 0.f, 0.f, 0.f);
            }
        }

        // compute: 4 k-steps of 8
#pragma unroll
        for (int ks = 0; ks < 4; ks++) {
            const int kc = ks * 8 + t;
            float afr[4][4], bfr[4][2];
#pragma unroll
            for (int mt = 0; mt < 4; mt++) {
                const int r = wm * 64 + mt * 16 + g;
                afr[mt][0] = As[(r    ) * SKS + kc];
                afr[mt][1] = As[(r + 8) * SKS + kc];
                afr[mt][2] = As[(r    ) * SKS + kc + 4];
                afr[mt][3] = As[(r + 8) * SKS + kc + 4];
            }
#pragma unroll
            for (int nt = 0; nt < 4; nt++) {
                const int n = wn * 32 + nt * 8 + g;
                bfr[nt][0] = Bs[n * SKS + kc];
                bfr[nt][1] = Bs[n * SKS + kc + 4];
            }
#pragma unroll
            for (int mt = 0; mt < 4; mt++)
#pragma unroll
                for (int nt = 0; nt < 4; nt++)
                    mma_tf32(acc[mt][nt], afr[mt], bfr[nt]);
        }
        __syncthreads();
    }

    // epilogue: d0:(g,2t) d1:(g,2t+1) d2:(g+8,2t) d3:(g+8,2t+1)
#pragma unroll
    for (int mt = 0; mt < 4; mt++) {
        const int row0 = m0 + wm * 64 + mt * 16 + g;
#pragma unroll
        for (int nt = 0; nt < 4; nt++) {
            const int col = n0 + wn * 32 + nt * 8 + 2 * t;
            float* c0 = C + (size_t)row0 * N + col;
            float* c1 = C + (size_t)(row0 + 8) * N + col;
            const float b0 = (bias && col     < N) ? bias[col]     : 0.f;
            const float b1 = (bias && col + 1 < N) ? bias[col + 1] : 0.f;
            if (col < N)     { c0[0] = acc[mt][nt][0] + b0; c1[0] = acc[mt][nt][2] + b0; }
            if (col + 1 < N) { c0[1] = acc[mt][nt][1] + b1; c1[1] = acc[mt][nt][3] + b1; }
        }
    }
}

// =====================================================================
// Kernel 3: fused scores + relative-position gather + softmax
// block = (q-tile of 32, h, b); 256 threads; writes g_attn[b,h,q,k]
// =====================================================================
constexpr int SQT_STRIDE = 36;   // sQt[d][q], padded
constexpr int SK_STRIDE  = 68;   // sK[k][d], padded
constexpr int SP_STRIDE  = 132;  // sP[q][t], padded
constexpr int SS_STRIDE  = 516;  // sS[q][k], padded
constexpr int SM3_QT = 0;
constexpr int SM3_K  = SM3_QT + 64 * SQT_STRIDE;
constexpr int SM3_P  = SM3_K  + 64 * SK_STRIDE;
constexpr int SM3_S  = SM3_P  + 32 * SP_STRIDE;
constexpr int SM3_F  = SM3_S  + 32 * SS_STRIDE;         // ints live here
constexpr int SM3_TOTAL = SM3_F + 32 * SS_STRIDE;
constexpr size_t SM3_BYTES = (size_t)SM3_TOTAL * 4;     // ~171.5 KB

__global__ __launch_bounds__(256) void scores_softmax_kernel(const int* __restrict__ fm)
{
    extern __shared__ float smem[];
    float* sQt = smem + SM3_QT;
    float* sK  = smem + SM3_K;
    float* sP  = smem + SM3_P;
    float* sS  = smem + SM3_S;
    int*   sF  = reinterpret_cast<int*>(smem + SM3_F);

    const int tid = threadIdx.x;
    const int q0  = blockIdx.x * 32;
    const int h   = blockIdx.y;
    const int b   = blockIdx.z;

    // --- load Q tile (transposed to [d][q]) ---
    {
        const int q = tid >> 3;
        const int dbase = (tid & 7) * 8;
        const float* src = g_Q + (size_t)(b * L + q0 + q) * HID + h * HD + dbase;
        float4 v0 = *reinterpret_cast<const float4*>(src);
        float4 v1 = *reinterpret_cast<const float4*>(src + 4);
        sQt[(dbase + 0) * SQT_STRIDE + q] = v0.x;
        sQt[(dbase + 1) * SQT_STRIDE + q] = v0.y;
        sQt[(dbase + 2) * SQT_STRIDE + q] = v0.z;
        sQt[(dbase + 3) * SQT_STRIDE + q] = v0.w;
        sQt[(dbase + 4) * SQT_STRIDE + q] = v1.x;
        sQt[(dbase + 5) * SQT_STRIDE + q] = v1.y;
        sQt[(dbase + 6) * SQT_STRIDE + q] = v1.z;
        sQt[(dbase + 7) * SQT_STRIDE + q] = v1.w;
    }
    for (int i = tid; i < 32 * TAB; i += 256) {
        const int q = i / TAB, t = i - q * TAB;
        sP[q * SP_STRIDE + t] = g_P[((size_t)(b * L + q0 + q) * H + h) * TAB + t];
    }
    {
        const int* src = fm + (size_t)(b * L + q0) * L;
        for (int i = tid; i < 32 * L; i += 256) {
            const int q = i >> 9, k = i & 511;
            sF[q * SS_STRIDE + k] = src[i];
        }
    }

    const int kl = tid >> 2;  // 0..63 local k
    const int qg = tid & 3;   // q group (8 q's each)

    for (int kt = 0; kt < 8; kt++) {
        __syncthreads();
        {
            const int krow = tid >> 2;
            const int dseg = (tid & 3) * 16;
            const float* src = g_K + (size_t)(b * L + kt * 64 + krow) * HID + h * HD + dseg;
            float* dst = sK + krow * SK_STRIDE + dseg;
#pragma unroll
            for (int j = 0; j < 4; j++)
                *reinterpret_cast<float4*>(dst + 4 * j) =
                    *reinterpret_cast<const float4*>(src + 4 * j);
        }
        __syncthreads();

        float acc[8];
#pragma unroll
        for (int i = 0; i < 8; i++) acc[i] = 0.f;
        const float* krow = sK + kl * SK_STRIDE;
#pragma unroll 8
        for (int d = 0; d < 64; d++) {
            const float kv = krow[d];
            const float* qr = sQt + d * SQT_STRIDE + qg * 8;
            float4 a0 = *reinterpret_cast<const float4*>(qr);
            float4 a1 = *reinterpret_cast<const float4*>(qr + 4);
            acc[0] += a0.x * kv; acc[1] += a0.y * kv;
            acc[2] += a0.z * kv; acc[3] += a0.w * kv;
            acc[4] += a1.x * kv; acc[5] += a1.y * kv;
            acc[6] += a1.z * kv; acc[7] += a1.w * kv;
        }
        const int kglob = kt * 64 + kl;
#pragma unroll
        for (int i = 0; i < 8; i++) {
            const int q = qg * 8 + i;
            const int t = sF[q * SS_STRIDE + kglob];
            sS[q * SS_STRIDE + kglob] = (acc[i] + sP[q * SP_STRIDE + t]) * 0.125f;
        }
    }
    __syncthreads();

    const int lane = tid & 31;
    const int warp = tid >> 5;
    for (int r = warp * 4; r < warp * 4 + 4; r++) {
        float* row = sS + r * SS_STRIDE;
        float m = -1e30f;
#pragma unroll
        for (int i = 0; i < 16; i++) m = fmaxf(m, row[lane + 32 * i]);
#pragma unroll
        for (int o = 16; o > 0; o >>= 1) m = fmaxf(m, __shfl_xor_sync(0xffffffffu, m, o));
        float s = 0.f;
#pragma unroll
        for (int i = 0; i < 16; i++) {
            const float e = __expf(row[lane + 32 * i] - m);
            row[lane + 32 * i] = e;
            s += e;
        }
#pragma unroll
        for (int o = 16; o > 0; o >>= 1) s += __shfl_xor_sync(0xffffffffu, s, o);
        const float inv = 1.f / s;
        float* dst = g_attn + ((size_t)(b * H + h) * L + (q0 + r)) * L;
#pragma unroll
        for (int i = 0; i < 16; i++) dst[lane + 32 * i] = row[lane + 32 * i] * inv;
    }
}

// =====================================================================
// Kernel 4: fused w1 = attn@V, bucket scatter S[t] += attn, w2 = S@table_v
// =====================================================================
constexpr int SM4_A  = 0;                      // sA[q][k] 32x516
constexpr int SM4_V  = SM4_A  + 32 * 516;      // sV[k][d] 64x68
constexpr int SM4_SB = SM4_V  + 64 * 68;       // buckets 32x132
constexpr int SM4_TV = SM4_SB + 32 * 132;      // table_v 129x64
constexpr int SM4_TOTAL = SM4_TV + TAB * 64;
constexpr size_t SM4_BYTES = (size_t)SM4_TOTAL * 4;  // ~130 KB

__global__ __launch_bounds__(256) void w12_kernel(const int* __restrict__ fm,
                                                  const float* __restrict__ table_v)
{
    extern __shared__ float smem[];
    float* sA  = smem + SM4_A;
    float* sV  = smem + SM4_V;
    float* sSb = smem + SM4_SB;
    float* sTv = smem + SM4_TV;

    const int tid = threadIdx.x;
    const int q0  = blockIdx.x * 32;
    const int h   = blockIdx.y;
    const int b   = blockIdx.z;

    {
        const float* asrc = g_attn + ((size_t)(b * H + h) * L + q0) * L;
        for (int i = tid; i < 32 * 512; i += 256) {
            const int q = i >> 9, k = i & 511;
            sA[q * 516 + k] = asrc[i];
        }
    }
    for (int i = tid; i < TAB * 64; i += 256) sTv[i] = table_v[i];
    for (int i = tid; i < 32 * 132; i += 256) sSb[i] = 0.f;

    const int q  = tid >> 3;
    const int dg = tid & 7;

    float acc1[8];
#pragma unroll
    for (int i = 0; i < 8; i++) acc1[i] = 0.f;

    for (int kt = 0; kt < 8; kt++) {
        __syncthreads();
        {
            const int krow = tid >> 2;
            const int dseg = (tid & 3) * 16;
            const float* src = g_V + (size_t)(b * L + kt * 64 + krow) * HID + h * HD + dseg;
            float* dst = sV + krow * 68 + dseg;
#pragma unroll
            for (int j = 0; j < 4; j++)
                *reinterpret_cast<float4*>(dst + 4 * j) =
                    *reinterpret_cast<const float4*>(src + 4 * j);
        }
        __syncthreads();

        const float* arow = sA + q * 516 + kt * 64;
#pragma unroll 8
        for (int k = 0; k < 64; k++) {
            const float a = arow[k];
            const float* vr = sV + k * 68 + dg * 8;
            float4 v0 = *reinterpret_cast<const float4*>(vr);
            float4 v1 = *reinterpret_cast<const float4*>(vr + 4);
            acc1[0] += a * v0.x; acc1[1] += a * v0.y;
            acc1[2] += a * v0.z; acc1[3] += a * v0.w;
            acc1[4] += a * v1.x; acc1[5] += a * v1.y;
            acc1[6] += a * v1.z; acc1[7] += a * v1.w;
        }
    }

    {
        const int kg = tid & 7;
        const int* fr = fm + (size_t)(b * L + q0 + q) * L;
        const float* ar = sA + q * 516;
        for (int i = 0; i < 64; i++) {
            const int k = i * 8 + kg;
            const int t = fr[k];
            atomicAdd(&sSb[q * 132 + t], ar[k]);
        }
    }
    __syncthreads();

    float acc2[8];
#pragma unroll
    for (int i = 0; i < 8; i++) acc2[i] = 0.f;
    const float* sbr = sSb + q * 132;
    for (int t = 0; t < TAB; t++) {
        const float s = sbr[t];
        const float* tvr = sTv + t * 64 + dg * 8;
        float4 v0 = *reinterpret_cast<const float4*>(tvr);
        float4 v1 = *reinterpret_cast<const float4*>(tvr + 4);
        acc2[0] += s * v0.x; acc2[1] += s * v0.y;
        acc2[2] += s * v0.z; acc2[3] += s * v0.w;
        acc2[4] += s * v1.x; acc2[5] += s * v1.y;
        acc2[6] += s * v1.z; acc2[7] += s * v1.w;
    }

    float* dst = g_X + (size_t)(b * L + q0 + q) * HID + h * HD + dg * 8;
    float4 o0 = make_float4(acc1[0] + acc2[0], acc1[1] + acc2[1],
                            acc1[2] + acc2[2], acc1[3] + acc2[3]);
    float4 o1 = make_float4(acc1[4] + acc2[4], acc1[5] + acc2[5],
                            acc1[6] + acc2[6], acc1[7] + acc2[7]);
    *reinterpret_cast<float4*>(dst)     = o0;
    *reinterpret_cast<float4*>(dst + 4) = o1;
}

// =====================================================================
// launch
// =====================================================================
extern "C" void kernel_launch(void* const* d_in, const int* in_sizes, int n_in,
                              void* d_out, int out_size)
{
    const float* query   = (const float*)d_in[0];
    const float* key     = (const float*)d_in[1];
    const float* value   = (const float*)d_in[2];
    const int*   fm      = (const int*)  d_in[3];
    const float* Wq      = (const float*)d_in[4];
    const float* bq      = (const float*)d_in[5];
    const float* Wk      = (const float*)d_in[6];
    const float* bk      = (const float*)d_in[7];
    const float* Wv      = (const float*)d_in[8];
    const float* bv      = (const float*)d_in[9];
    const float* Wo      = (const float*)d_in[10];
    const float* bo      = (const float*)d_in[11];
    const float* table_k = (const float*)d_in[12];
    const float* table_v = (const float*)d_in[13];
    float* out = (float*)d_out;

    cudaFuncSetAttribute(scores_softmax_kernel,
                         cudaFuncAttributeMaxDynamicSharedMemorySize, (int)SM3_BYTES);
    cudaFuncSetAttribute(w12_kernel,
                         cudaFuncAttributeMaxDynamicSharedMemorySize, (int)SM4_BYTES);

    float* gQ; cudaGetSymbolAddress((void**)&gQ, g_Q);
    float* gX; cudaGetSymbolAddress((void**)&gX, g_X);
    float* gP; cudaGetSymbolAddress((void**)&gP, g_P);
    float* gK; cudaGetSymbolAddress((void**)&gK, g_K);
    float* gV; cudaGetSymbolAddress((void**)&gV, g_V);

    const dim3 gproj(HID / 128, BL / 128);  // (8, 32)
    gemm_tf32<<<gproj, 256>>>(query, Wq, bq, gQ, BL, HID, HID);
    gemm_tf32<<<gproj, 256>>>(key,   Wk, bk, gK, BL, HID, HID);
    gemm_tf32<<<gproj, 256>>>(value, Wv, bv, gV, BL, HID, HID);

    // P[b,q,h,t] : [65536, 64] @ [129, 64]^T
    const dim3 gridP((TAB + 127) / 128, (BL * H) / 128);  // (2, 512)
    gemm_tf32<<<gridP, 256>>>(gQ, table_k, nullptr, gP, BL * H, TAB, HD);

    const dim3 gattn(L / 32, H, B);  // (16, 16, 8)
    scores_softmax_kernel<<<gattn, 256, SM3_BYTES>>>(fm);
    w12_kernel<<<gattn, 256, SM4_BYTES>>>(fm, table_v);

    gemm_tf32<<<gproj, 256>>>(gX, Wo, bo, out, BL, HID, HID);
}

// round 4
// speedup vs baseline: 1.9666x; 1.4916x over previous
#include <cuda_runtime.h>

// ---------------- problem constants ----------------
constexpr int B    = 8;
constexpr int L    = 512;
constexpr int HID  = 1024;
constexpr int H    = 16;
constexpr int HD   = 64;     // head dim
constexpr int TAB  = 129;    // 2*64+1 relative-position table rows
constexpr int BL   = B * L;  // 4096

// ---------------- device scratch ----------------
__device__ float g_Q[BL * HID];
__device__ float g_K[BL * HID];
__device__ float g_V[BL * HID];
__device__ float g_X[BL * HID];   // w1+w2 merged, [B,L,HID]

// =====================================================================
// tf32 tensor-core GEMM: C[M,N] = A[M,K] @ W[N,K]^T (+bias)
// =====================================================================
__device__ __forceinline__ float tf32r(float x) {
    unsigned y;
    asm("cvt.rna.tf32.f32 %0, %1;" : "=r"(y) : "f"(x));
    return __uint_as_float(y);
}

__device__ __forceinline__ void mma_tf32(float d[4], const float a[4], const float b[2]) {
    unsigned const* A = reinterpret_cast<unsigned const*>(a);
    unsigned const* Bp = reinterpret_cast<unsigned const*>(b);
    asm volatile(
        "mma.sync.aligned.m16n8k8.row.col.f32.tf32.tf32.f32 "
        "{%0,%1,%2,%3}, {%4,%5,%6,%7}, {%8,%9}, {%0,%1,%2,%3};"
        : "+f"(d[0]), "+f"(d[1]), "+f"(d[2]), "+f"(d[3])
        : "r"(A[0]), "r"(A[1]), "r"(A[2]), "r"(A[3]),
          "r"(Bp[0]), "r"(Bp[1]));
}

constexpr int SKS = 36;

__global__ __launch_bounds__(256) void gemm_tf32(
    const float* __restrict__ A, const float* __restrict__ W,
    const float* __restrict__ bias, float* __restrict__ C,
    int M, int N, int K)
{
    __shared__ float As[128 * SKS];
    __shared__ float Bs[128 * SKS];

    const int tid  = threadIdx.x;
    const int m0   = blockIdx.y * 128;
    const int n0   = blockIdx.x * 128;
    const int lane = tid & 31;
    const int g    = lane >> 2;
    const int t    = lane & 3;
    const int warp = tid >> 5;
    const int wm   = warp & 1;
    const int wn   = warp >> 1;

    const int lrow = tid >> 1;
    const int lc   = (tid & 1) * 16;
    const float* Ap = A + (size_t)(m0 + lrow) * K + lc;
    const bool  wok = (n0 + lrow) < N;
    const float* Wp = W + (size_t)(n0 + lrow) * K + lc;

    float acc[4][4][4];
#pragma unroll
    for (int i = 0; i < 4; i++)
#pragma unroll
        for (int j = 0; j < 4; j++)
#pragma unroll
            for (int r = 0; r < 4; r++) acc[i][j][r] = 0.f;

    float4 ar[4], wr[4];
#pragma unroll
    for (int j = 0; j < 4; j++) {
        ar[j] = *reinterpret_cast<const float4*>(Ap + 4 * j);
        wr[j] = wok ? *reinterpret_cast<const float4*>(Wp + 4 * j)
                    : make_float4(0.f, 0.f, 0.f, 0.f);
    }

    for (int k0 = 0; k0 < K; k0 += 32) {
        float* asd = As + lrow * SKS + lc;
        float* bsd = Bs + lrow * SKS + lc;
#pragma unroll
        for (int j = 0; j < 4; j++) {
            float4 av = make_float4(tf32r(ar[j].x), tf32r(ar[j].y), tf32r(ar[j].z), tf32r(ar[j].w));
            float4 wv = make_float4(tf32r(wr[j].x), tf32r(wr[j].y), tf32r(wr[j].z), tf32r(wr[j].w));
            *reinterpret_cast<float4*>(asd + 4 * j) = av;
            *reinterpret_cast<float4*>(bsd + 4 * j) = wv;
        }
        __syncthreads();

        if (k0 + 32 < K) {
#pragma unroll
            for (int j = 0; j < 4; j++) {
                ar[j] = *reinterpret_cast<const float4*>(Ap + k0 + 32 + 4 * j);
                wr[j] = wok ? *reinterpret_cast<const float4*>(Wp + k0 + 32 + 4 * j)
                            : make_float4(0.f, 0.f, 0.f, 0.f);
            }
        }

#pragma unroll
        for (int ks = 0; ks < 4; ks++) {
            const int kc = ks * 8 + t;
            float afr[4][4], bfr[4][2];
#pragma unroll
            for (int mt = 0; mt < 4; mt++) {
                const int r = wm * 64 + mt * 16 + g;
                afr[mt][0] = As[(r    ) * SKS + kc];
                afr[mt][1] = As[(r + 8) * SKS + kc];
                afr[mt][2] = As[(r    ) * SKS + kc + 4];
                afr[mt][3] = As[(r + 8) * SKS + kc + 4];
            }
#pragma unroll
            for (int nt = 0; nt < 4; nt++) {
                const int n = wn * 32 + nt * 8 + g;
                bfr[nt][0] = Bs[n * SKS + kc];
                bfr[nt][1] = Bs[n * SKS + kc + 4];
            }
#pragma unroll
            for (int mt = 0; mt < 4; mt++)
#pragma unroll
                for (int nt = 0; nt < 4; nt++)
                    mma_tf32(acc[mt][nt], afr[mt], bfr[nt]);
        }
        __syncthreads();
    }

#pragma unroll
    for (int mt = 0; mt < 4; mt++) {
        const int row0 = m0 + wm * 64 + mt * 16 + g;
#pragma unroll
        for (int nt = 0; nt < 4; nt++) {
            const int col = n0 + wn * 32 + nt * 8 + 2 * t;
            float* c0 = C + (size_t)row0 * N + col;
            float* c1 = C + (size_t)(row0 + 8) * N + col;
            const float b0 = (bias && col     < N) ? bias[col]     : 0.f;
            const float b1 = (bias && col + 1 < N) ? bias[col + 1] : 0.f;
            if (col < N)     { c0[0] = acc[mt][nt][0] + b0; c1[0] = acc[mt][nt][2] + b0; }
            if (col + 1 < N) { c0[1] = acc[mt][nt][1] + b1; c1[1] = acc[mt][nt][3] + b1; }
        }
    }
}

// =====================================================================
// Fully fused attention: P = Q·table_k^T (in-block), scores + gather +
// softmax + w1=attn@V + bucket scatter + w2 = S@table_v, all in SMEM.
// block = (q-tile of 32, h, b); 512 threads.
// =====================================================================
// SMEM layout (float offsets):
//  union region U (12480):
//    part1: sQt @ 0   (64*36=2304),  sP @ 2304 (32*132=4224)
//    part2: sTv @ 0   (129*64=8256), sSb @ 8256 (32*132=4224)
//  sKV @ 12480 (128*68 = 8704)         K tiles then V tiles
//  sS  @ 21184 (32*516 = 16512)        scores/attn; temporarily table_k (129*68=8772)
//  sF  @ 37696 (bytes, 32*516 = 16512B = 4128 floats)
constexpr int OFF_U   = 0;
constexpr int OFF_QT  = OFF_U;            // stride 36
constexpr int OFF_P   = OFF_U + 2304;     // stride 132
constexpr int OFF_TV  = OFF_U;            // stride 64
constexpr int OFF_SB  = OFF_U + 8256;     // stride 132
constexpr int OFF_KV  = 12480;            // stride 68
constexpr int OFF_S   = 21184;            // stride 516
constexpr int OFF_TK  = 21184;            // stride 68 (temp, dead before scores)
constexpr int OFF_F   = 37696;            // bytes, stride 516
constexpr int SMF_TOTAL = 41824;
constexpr size_t SMF_BYTES = (size_t)SMF_TOTAL * 4;   // 167,296 B

__global__ __launch_bounds__(512) void attn_fused_kernel(
    const int* __restrict__ fm,
    const float* __restrict__ table_k,
    const float* __restrict__ table_v)
{
    extern __shared__ float smem[];
    float*  sQt = smem + OFF_QT;
    float*  sP  = smem + OFF_P;
    float*  sKV = smem + OFF_KV;
    float*  sS  = smem + OFF_S;
    float*  sTk = smem + OFF_TK;
    float*  sTv = smem + OFF_TV;
    float*  sSb = smem + OFF_SB;
    unsigned char* sFb = reinterpret_cast<unsigned char*>(smem + OFF_F);

    const int tid = threadIdx.x;
    const int q0  = blockIdx.x * 32;
    const int h   = blockIdx.y;
    const int b   = blockIdx.z;

    // ---------- stage 0: load Q (transposed), table_k (into sS temp), fm (bytes) ----------
    {
        const int q = tid >> 4;
        const int dbase = (tid & 15) * 4;
        const float* src = g_Q + (size_t)(b * L + q0 + q) * HID + h * HD + dbase;
        float4 v = *reinterpret_cast<const float4*>(src);
        sQt[(dbase + 0) * 36 + q] = v.x;
        sQt[(dbase + 1) * 36 + q] = v.y;
        sQt[(dbase + 2) * 36 + q] = v.z;
        sQt[(dbase + 3) * 36 + q] = v.w;
    }
    for (int i = tid; i < TAB * 64; i += 512) {
        const int t = i >> 6, d = i & 63;
        sTk[t * 68 + d] = table_k[i];
    }
    for (int i = tid; i < 32 * 128; i += 512) {
        const int q = i >> 7;
        const int kq = (i & 127) * 4;
        const int4 v = *reinterpret_cast<const int4*>(
            fm + (size_t)(b * L + q0 + q) * L + kq);
        uchar4 pk = make_uchar4((unsigned char)v.x, (unsigned char)v.y,
                                (unsigned char)v.z, (unsigned char)v.w);
        *reinterpret_cast<uchar4*>(sFb + q * 516 + kq) = pk;
    }
    __syncthreads();

    // ---------- stage 1: P[q][t] = Q[q,:]·table_k[t,:]  (fp32) ----------
    {
        const int tl = tid >> 2;   // 0..127
        const int qg = tid & 3;
        float acc[8];
#pragma unroll
        for (int i = 0; i < 8; i++) acc[i] = 0.f;
        const float* tkr = sTk + tl * 68;
#pragma unroll 8
        for (int d = 0; d < 64; d++) {
            const float tk = tkr[d];
            const float* qr = sQt + d * 36 + qg * 8;
            float4 a0 = *reinterpret_cast<const float4*>(qr);
            float4 a1 = *reinterpret_cast<const float4*>(qr + 4);
            acc[0] += a0.x * tk; acc[1] += a0.y * tk;
            acc[2] += a0.z * tk; acc[3] += a0.w * tk;
            acc[4] += a1.x * tk; acc[5] += a1.y * tk;
            acc[6] += a1.z * tk; acc[7] += a1.w * tk;
        }
#pragma unroll
        for (int i = 0; i < 8; i++) sP[(qg * 8 + i) * 132 + tl] = acc[i];
        // last table row t = 128
        if (tid < 32) {
            const int q = tid;
            float s = 0.f;
            const float* tkr2 = sTk + 128 * 68;
#pragma unroll 8
            for (int d = 0; d < 64; d++) s += sQt[d * 36 + q] * tkr2[d];
            sP[q * 132 + 128] = s;
        }
    }
    __syncthreads();   // sTk (in sS region) dead after this point

    // ---------- stage 2: scores + gather, k-tiles of 128 ----------
    const int kl = tid >> 2;   // 0..127
    const int qg = tid & 3;
    for (int kt = 0; kt < 4; kt++) {
        __syncthreads();
        {
            const int krow = tid >> 2;
            const int dseg = (tid & 3) * 16;
            const float* src = g_K + (size_t)(b * L + kt * 128 + krow) * HID + h * HD + dseg;
            float* dst = sKV + krow * 68 + dseg;
#pragma unroll
            for (int j = 0; j < 4; j++)
                *reinterpret_cast<float4*>(dst + 4 * j) =
                    *reinterpret_cast<const float4*>(src + 4 * j);
        }
        __syncthreads();

        float acc[8];
#pragma unroll
        for (int i = 0; i < 8; i++) acc[i] = 0.f;
        const float* krow = sKV + kl * 68;
#pragma unroll 8
        for (int d = 0; d < 64; d++) {
            const float kv = krow[d];
            const float* qr = sQt + d * 36 + qg * 8;
            float4 a0 = *reinterpret_cast<const float4*>(qr);
            float4 a1 = *reinterpret_cast<const float4*>(qr + 4);
            acc[0] += a0.x * kv; acc[1] += a0.y * kv;
            acc[2] += a0.z * kv; acc[3] += a0.w * kv;
            acc[4] += a1.x * kv; acc[5] += a1.y * kv;
            acc[6] += a1.z * kv; acc[7] += a1.w * kv;
        }
        const int kglob = kt * 128 + kl;
#pragma unroll
        for (int i = 0; i < 8; i++) {
            const int q = qg * 8 + i;
            const int t = sFb[q * 516 + kglob];
            sS[q * 516 + kglob] = (acc[i] + sP[q * 132 + t]) * 0.125f;
        }
    }
    __syncthreads();

    // ---------- stage 3: softmax (16 warps x 2 rows) ----------
    {
        const int lane = tid & 31;
        const int warp = tid >> 5;
        for (int r = warp * 2; r < warp * 2 + 2; r++) {
            float* row = sS + r * 516;
            float m = -1e30f;
#pragma unroll
            for (int i = 0; i < 16; i++) m = fmaxf(m, row[lane + 32 * i]);
#pragma unroll
            for (int o = 16; o > 0; o >>= 1) m = fmaxf(m, __shfl_xor_sync(0xffffffffu, m, o));
            float s = 0.f;
#pragma unroll
            for (int i = 0; i < 16; i++) {
                const float e = __expf(row[lane + 32 * i] - m);
                row[lane + 32 * i] = e;
                s += e;
            }
#pragma unroll
            for (int o = 16; o > 0; o >>= 1) s += __shfl_xor_sync(0xffffffffu, s, o);
            const float inv = 1.f / s;
#pragma unroll
            for (int i = 0; i < 16; i++) row[lane + 32 * i] *= inv;
        }
    }
    __syncthreads();   // sP dead; union region becomes sTv + sSb

    // ---------- stage 4: load table_v, zero buckets ----------
    for (int i = tid; i < TAB * 64; i += 512) sTv[i] = table_v[i];
    for (int i = tid; i < 32 * 132; i += 512) sSb[i] = 0.f;

    // ---------- stage 5: w1 = attn @ V ----------
    const int q  = tid >> 4;
    const int dg = tid & 15;
    float acc1[4];
#pragma unroll
    for (int i = 0; i < 4; i++) acc1[i] = 0.f;

    for (int kt = 0; kt < 4; kt++) {
        __syncthreads();
        {
            const int krow = tid >> 2;
            const int dseg = (tid & 3) * 16;
            const float* src = g_V + (size_t)(b * L + kt * 128 + krow) * HID + h * HD + dseg;
            float* dst = sKV + krow * 68 + dseg;
#pragma unroll
            for (int j = 0; j < 4; j++)
                *reinterpret_cast<float4*>(dst + 4 * j) =
                    *reinterpret_cast<const float4*>(src + 4 * j);
        }
        __syncthreads();

        const float* arow = sS + q * 516 + kt * 128;
#pragma unroll 8
        for (int k = 0; k < 128; k++) {
            const float a = arow[k];
            float4 v = *reinterpret_cast<const float4*>(sKV + k * 68 + dg * 4);
            acc1[0] += a * v.x; acc1[1] += a * v.y;
            acc1[2] += a * v.z; acc1[3] += a * v.w;
        }
    }

    // ---------- stage 6: bucket scatter S[q][t] += attn[q][k] ----------
    {
        const int kg = tid & 15;
        const unsigned char* fr = sFb + q * 516;
        const float* ar = sS + q * 516;
        float* sbq = sSb + q * 132;
#pragma unroll 4
        for (int i = 0; i < 32; i++) {
            const int k = i * 16 + kg;
            atomicAdd(&sbq[fr[k]], ar[k]);
        }
    }
    __syncthreads();

    // ---------- stage 7: w2 = S @ table_v, write out ----------
    float acc2[4];
#pragma unroll
    for (int i = 0; i < 4; i++) acc2[i] = 0.f;
    const float* sbr = sSb + q * 132;
#pragma unroll 4
    for (int t = 0; t < TAB; t++) {
        const float s = sbr[t];
        float4 tv = *reinterpret_cast<const float4*>(sTv + t * 64 + dg * 4);
        acc2[0] += s * tv.x; acc2[1] += s * tv.y;
        acc2[2] += s * tv.z; acc2[3] += s * tv.w;
    }

    float* dst = g_X + (size_t)(b * L + q0 + q) * HID + h * HD + dg * 4;
    float4 o = make_float4(acc1[0] + acc2[0], acc1[1] + acc2[1],
                           acc1[2] + acc2[2], acc1[3] + acc2[3]);
    *reinterpret_cast<float4*>(dst) = o;
}

// =====================================================================
// launch
// =====================================================================
extern "C" void kernel_launch(void* const* d_in, const int* in_sizes, int n_in,
                              void* d_out, int out_size)
{
    const float* query   = (const float*)d_in[0];
    const float* key     = (const float*)d_in[1];
    const float* value   = (const float*)d_in[2];
    const int*   fm      = (const int*)  d_in[3];
    const float* Wq      = (const float*)d_in[4];
    const float* bq      = (const float*)d_in[5];
    const float* Wk      = (const float*)d_in[6];
    const float* bk      = (const float*)d_in[7];
    const float* Wv      = (const float*)d_in[8];
    const float* bv      = (const float*)d_in[9];
    const float* Wo      = (const float*)d_in[10];
    const float* bo      = (const float*)d_in[11];
    const float* table_k = (const float*)d_in[12];
    const float* table_v = (const float*)d_in[13];
    float* out = (float*)d_out;

    cudaFuncSetAttribute(attn_fused_kernel,
                         cudaFuncAttributeMaxDynamicSharedMemorySize, (int)SMF_BYTES);

    float* gQ; cudaGetSymbolAddress((void**)&gQ, g_Q);
    float* gK; cudaGetSymbolAddress((void**)&gK, g_K);
    float* gV; cudaGetSymbolAddress((void**)&gV, g_V);
    float* gX; cudaGetSymbolAddress((void**)&gX, g_X);

    const dim3 gproj(HID / 128, BL / 128);  // (8, 32)
    gemm_tf32<<<gproj, 256>>>(query, Wq, bq, gQ, BL, HID, HID);
    gemm_tf32<<<gproj, 256>>>(key,   Wk, bk, gK, BL, HID, HID);
    gemm_tf32<<<gproj, 256>>>(value, Wv, bv, gV, BL, HID, HID);

    const dim3 gattn(L / 32, H, B);  // (16, 16, 8)
    attn_fused_kernel<<<gattn, 512, SMF_BYTES>>>(fm, table_k, table_v);

    gemm_tf32<<<gproj, 256>>>(gX, Wo, bo, out, BL, HID, HID);
}

// round 5
// speedup vs baseline: 3.1562x; 1.6049x over previous
#include <cuda_runtime.h>

// ---------------- problem constants ----------------
constexpr int B    = 8;
constexpr int L    = 512;
constexpr int HID  = 1024;
constexpr int H    = 16;
constexpr int HD   = 64;     // head dim
constexpr int TAB  = 129;    // 2*64+1 relative-position table rows
constexpr int BL   = B * L;  // 4096

// ---------------- device scratch ----------------
__device__ float g_Q[BL * HID];
__device__ float g_K[BL * HID];
__device__ float g_V[BL * HID];
__device__ float g_X[BL * HID];   // w1+w2 merged, [B,L,HID]

// =====================================================================
// tf32 helpers (fragment mapping validated in R3 gemm)
// =====================================================================
__device__ __forceinline__ float tf32r(float x) {
    unsigned y;
    asm("cvt.rna.tf32.f32 %0, %1;" : "=r"(y) : "f"(x));
    return __uint_as_float(y);
}

__device__ __forceinline__ void mma_tf32(float d[4], const float a[4], const float b[2]) {
    unsigned const* A = reinterpret_cast<unsigned const*>(a);
    unsigned const* Bp = reinterpret_cast<unsigned const*>(b);
    asm volatile(
        "mma.sync.aligned.m16n8k8.row.col.f32.tf32.tf32.f32 "
        "{%0,%1,%2,%3}, {%4,%5,%6,%7}, {%8,%9}, {%0,%1,%2,%3};"
        : "+f"(d[0]), "+f"(d[1]), "+f"(d[2]), "+f"(d[3])
        : "r"(A[0]), "r"(A[1]), "r"(A[2]), "r"(A[3]),
          "r"(Bp[0]), "r"(Bp[1]));
}

// =====================================================================
// tf32 GEMM for projections: C[M,N] = A[M,K] @ W[N,K]^T (+bias)
// (unchanged from R3 — 42us per 4096x1024x1024)
// =====================================================================
constexpr int SKS = 36;

__global__ __launch_bounds__(256) void gemm_tf32(
    const float* __restrict__ A, const float* __restrict__ W,
    const float* __restrict__ bias, float* __restrict__ C,
    int M, int N, int K)
{
    __shared__ float As[128 * SKS];
    __shared__ float Bs[128 * SKS];

    const int tid  = threadIdx.x;
    const int m0   = blockIdx.y * 128;
    const int n0   = blockIdx.x * 128;
    const int lane = tid & 31;
    const int g    = lane >> 2;
    const int t    = lane & 3;
    const int warp = tid >> 5;
    const int wm   = warp & 1;
    const int wn   = warp >> 1;

    const int lrow = tid >> 1;
    const int lc   = (tid & 1) * 16;
    const float* Ap = A + (size_t)(m0 + lrow) * K + lc;
    const bool  wok = (n0 + lrow) < N;
    const float* Wp = W + (size_t)(n0 + lrow) * K + lc;

    float acc[4][4][4];
#pragma unroll
    for (int i = 0; i < 4; i++)
#pragma unroll
        for (int j = 0; j < 4; j++)
#pragma unroll
            for (int r = 0; r < 4; r++) acc[i][j][r] = 0.f;

    float4 ar[4], wr[4];
#pragma unroll
    for (int j = 0; j < 4; j++) {
        ar[j] = *reinterpret_cast<const float4*>(Ap + 4 * j);
        wr[j] = wok ? *reinterpret_cast<const float4*>(Wp + 4 * j)
                    : make_float4(0.f, 0.f, 0.f, 0.f);
    }

    for (int k0 = 0; k0 < K; k0 += 32) {
        float* asd = As + lrow * SKS + lc;
        float* bsd = Bs + lrow * SKS + lc;
#pragma unroll
        for (int j = 0; j < 4; j++) {
            float4 av = make_float4(tf32r(ar[j].x), tf32r(ar[j].y), tf32r(ar[j].z), tf32r(ar[j].w));
            float4 wv = make_float4(tf32r(wr[j].x), tf32r(wr[j].y), tf32r(wr[j].z), tf32r(wr[j].w));
            *reinterpret_cast<float4*>(asd + 4 * j) = av;
            *reinterpret_cast<float4*>(bsd + 4 * j) = wv;
        }
        __syncthreads();

        if (k0 + 32 < K) {
#pragma unroll
            for (int j = 0; j < 4; j++) {
                ar[j] = *reinterpret_cast<const float4*>(Ap + k0 + 32 + 4 * j);
                wr[j] = wok ? *reinterpret_cast<const float4*>(Wp + k0 + 32 + 4 * j)
                            : make_float4(0.f, 0.f, 0.f, 0.f);
            }
        }

#pragma unroll
        for (int ks = 0; ks < 4; ks++) {
            const int kc = ks * 8 + t;
            float afr[4][4], bfr[4][2];
#pragma unroll
            for (int mt = 0; mt < 4; mt++) {
                const int r = wm * 64 + mt * 16 + g;
                afr[mt][0] = As[(r    ) * SKS + kc];
                afr[mt][1] = As[(r + 8) * SKS + kc];
                afr[mt][2] = As[(r    ) * SKS + kc + 4];
                afr[mt][3] = As[(r + 8) * SKS + kc + 4];
            }
#pragma unroll
            for (int nt = 0; nt < 4; nt++) {
                const int n = wn * 32 + nt * 8 + g;
                bfr[nt][0] = Bs[n * SKS + kc];
                bfr[nt][1] = Bs[n * SKS + kc + 4];
            }
#pragma unroll
            for (int mt = 0; mt < 4; mt++)
#pragma unroll
                for (int nt = 0; nt < 4; nt++)
                    mma_tf32(acc[mt][nt], afr[mt], bfr[nt]);
        }
        __syncthreads();
    }

#pragma unroll
    for (int mt = 0; mt < 4; mt++) {
        const int row0 = m0 + wm * 64 + mt * 16 + g;
#pragma unroll
        for (int nt = 0; nt < 4; nt++) {
            const int col = n0 + wn * 32 + nt * 8 + 2 * t;
            float* c0 = C + (size_t)row0 * N + col;
            float* c1 = C + (size_t)(row0 + 8) * N + col;
            const float b0 = (bias && col     < N) ? bias[col]     : 0.f;
            const float b1 = (bias && col + 1 < N) ? bias[col + 1] : 0.f;
            if (col < N)     { c0[0] = acc[mt][nt][0] + b0; c1[0] = acc[mt][nt][2] + b0; }
            if (col + 1 < N) { c0[1] = acc[mt][nt][1] + b1; c1[1] = acc[mt][nt][3] + b1; }
        }
    }
}

// =====================================================================
// Fully fused MMA attention. block = (32 q, h, b), 512 threads, 16 warps.
// P, scores, w1, w2 all on tf32 m16n8k8. attn never leaves SMEM.
//
// SMEM layout (float offsets):
//  sQ  @ 0      [32][68]                       (union w/ sSb [32][136] later)
//  sP  @ 2176   [32][132]
//  sKV @ 6400   staging: table_k[136][68] -> K halves [256][68]
//               -> V halves [256][72] -> table_v [136][72]
//  sS  @ 24832  [32][516]  logits / attn
//  sF  @ 41344  [32][516] bytes (final_mat as uchar)
// =====================================================================
constexpr int OFF_P  = 2176;
constexpr int OFF_KV = 6400;
constexpr int OFF_S  = 24832;
constexpr int OFF_F  = 41344;
constexpr int SMF_TOTAL = OFF_F + 4128;           // 45472 floats
constexpr size_t SMF_BYTES = (size_t)SMF_TOTAL * 4;  // 181,888 B

__global__ __launch_bounds__(512) void attn_fused_mma(
    const int* __restrict__ fm,
    const float* __restrict__ table_k,
    const float* __restrict__ table_v)
{
    extern __shared__ float smem[];
    float* sQ  = smem;                 // [32][68]
    float* sP  = smem + OFF_P;         // [32][132]
    float* sSb = smem;                 // [32][136] union (after sQ/sP dead)
    float* sKV = smem + OFF_KV;
    float* sS  = smem + OFF_S;         // [32][516]
    unsigned char* sFb = reinterpret_cast<unsigned char*>(smem + OFF_F);

    const int tid  = threadIdx.x;
    const int lane = tid & 31;
    const int warp = tid >> 5;
    const int g    = lane >> 2;
    const int t    = lane & 3;
    const int q0   = blockIdx.x * 32;
    const int h    = blockIdx.y;
    const int b    = blockIdx.z;

    // ---------- stage 0: stage Q (tf32), table_k (tf32, padded to 136), fm ----------
    {
        const int q = tid >> 4;
        const int dbase = (tid & 15) * 4;
        float4 v = *reinterpret_cast<const float4*>(
            g_Q + (size_t)(b * L + q0 + q) * HID + h * HD + dbase);
        float4 rv = make_float4(tf32r(v.x), tf32r(v.y), tf32r(v.z), tf32r(v.w));
        *reinterpret_cast<float4*>(sQ + q * 68 + dbase) = rv;
    }
    for (int i = tid; i < 136 * 16; i += 512) {
        const int r = i >> 4, sg = (i & 15) * 4;
        float4 v = make_float4(0.f, 0.f, 0.f, 0.f);
        if (r < TAB) v = *reinterpret_cast<const float4*>(table_k + r * 64 + sg);
        float4 rv = make_float4(tf32r(v.x), tf32r(v.y), tf32r(v.z), tf32r(v.w));
        *reinterpret_cast<float4*>(sKV + r * 68 + sg) = rv;
    }
    for (int i = tid; i < 32 * 128; i += 512) {
        const int q = i >> 7;
        const int kq = (i & 127) * 4;
        const int4 v = *reinterpret_cast<const int4*>(
            fm + (size_t)(b * L + q0 + q) * L + kq);
        uchar4 pk = make_uchar4((unsigned char)v.x, (unsigned char)v.y,
                                (unsigned char)v.z, (unsigned char)v.w);
        *reinterpret_cast<uchar4*>(sFb + q * 516 + kq) = pk;
    }
    __syncthreads();

    // ---------- stage 1: P[32][129] = Q @ table_k^T  (MMA, 34 m16n8 tiles) ----------
    for (int tile = warp; tile < 34; tile += 16) {
        const int mh = tile / 17, n8 = tile % 17;
        const int mr = mh * 16, nb = n8 * 8;
        float acc[4] = {0.f, 0.f, 0.f, 0.f};
#pragma unroll
        for (int ks = 0; ks < 8; ks++) {
            const int kb = ks * 8;
            float a[4], bb[2];
            a[0] = sQ[(mr + g    ) * 68 + kb + t];
            a[1] = sQ[(mr + g + 8) * 68 + kb + t];
            a[2] = sQ[(mr + g    ) * 68 + kb + t + 4];
            a[3] = sQ[(mr + g + 8) * 68 + kb + t + 4];
            bb[0] = sKV[(nb + g) * 68 + kb + t];
            bb[1] = sKV[(nb + g) * 68 + kb + t + 4];
            mma_tf32(acc, a, bb);
        }
        const int c0 = nb + 2 * t;
        if (c0 < TAB) {
            sP[(mr + g    ) * 132 + c0] = acc[0];
            sP[(mr + g + 8) * 132 + c0] = acc[2];
        }
        if (c0 + 1 < TAB) {
            sP[(mr + g    ) * 132 + c0 + 1] = acc[1];
            sP[(mr + g + 8) * 132 + c0 + 1] = acc[3];
        }
    }
    __syncthreads();

    // ---------- stage 2: scores = Q@K^T + gather(P) , K in 2 halves of 256 ----------
    for (int half = 0; half < 2; half++) {
        for (int i = tid; i < 256 * 16; i += 512) {
            const int r = i >> 4, sg = (i & 15) * 4;
            float4 v = *reinterpret_cast<const float4*>(
                g_K + (size_t)(b * L + half * 256 + r) * HID + h * HD + sg);
            float4 rv = make_float4(tf32r(v.x), tf32r(v.y), tf32r(v.z), tf32r(v.w));
            *reinterpret_cast<float4*>(sKV + r * 68 + sg) = rv;
        }
        __syncthreads();

        for (int tile = warp; tile < 64; tile += 16) {
            const int mh = tile >> 5, n8 = tile & 31;
            const int mr = mh * 16, nb = n8 * 8;
            float acc[4] = {0.f, 0.f, 0.f, 0.f};
#pragma unroll
            for (int ks = 0; ks < 8; ks++) {
                const int kb = ks * 8;
                float a[4], bb[2];
                a[0] = sQ[(mr + g    ) * 68 + kb + t];
                a[1] = sQ[(mr + g + 8) * 68 + kb + t];
                a[2] = sQ[(mr + g    ) * 68 + kb + t + 4];
                a[3] = sQ[(mr + g + 8) * 68 + kb + t + 4];
                bb[0] = sKV[(nb + g) * 68 + kb + t];
                bb[1] = sKV[(nb + g) * 68 + kb + t + 4];
                mma_tf32(acc, a, bb);
            }
            const int row0 = mr + g, row1 = row0 + 8;
            const int kc = half * 256 + nb + 2 * t;
            const int t00 = sFb[row0 * 516 + kc], t01 = sFb[row0 * 516 + kc + 1];
            const int t10 = sFb[row1 * 516 + kc], t11 = sFb[row1 * 516 + kc + 1];
            sS[row0 * 516 + kc    ] = (acc[0] + sP[row0 * 132 + t00]) * 0.125f;
            sS[row0 * 516 + kc + 1] = (acc[1] + sP[row0 * 132 + t01]) * 0.125f;
            sS[row1 * 516 + kc    ] = (acc[2] + sP[row1 * 132 + t10]) * 0.125f;
            sS[row1 * 516 + kc + 1] = (acc[3] + sP[row1 * 132 + t11]) * 0.125f;
        }
        __syncthreads();
    }

    // ---------- stage 3: softmax (16 warps x 2 rows), write tf32-rounded attn ----------
    for (int r = warp * 2; r < warp * 2 + 2; r++) {
        float* row = sS + r * 516;
        float m = -1e30f;
#pragma unroll
        for (int i = 0; i < 16; i++) m = fmaxf(m, row[lane + 32 * i]);
#pragma unroll
        for (int o = 16; o > 0; o >>= 1) m = fmaxf(m, __shfl_xor_sync(0xffffffffu, m, o));
        float e[16];
        float s = 0.f;
#pragma unroll
        for (int i = 0; i < 16; i++) {
            e[i] = __expf(row[lane + 32 * i] - m);
            s += e[i];
        }
#pragma unroll
        for (int o = 16; o > 0; o >>= 1) s += __shfl_xor_sync(0xffffffffu, s, o);
        const float inv = 1.f / s;
#pragma unroll
        for (int i = 0; i < 16; i++) row[lane + 32 * i] = tf32r(e[i] * inv);
    }
    __syncthreads();

    // zero buckets (sQ/sP region now dead)
    for (int i = tid; i < 32 * 136; i += 512) sSb[i] = 0.f;

    // ---------- stage 4: w1 = attn @ V (warp = one m16n8 tile of 32x64) ----------
    const int mhw = warp >> 3, n8w = warp & 7;
    const int mrw = mhw * 16, nbw = n8w * 8;
    float acc1[4] = {0.f, 0.f, 0.f, 0.f};
    for (int half = 0; half < 2; half++) {
        for (int i = tid; i < 256 * 16; i += 512) {
            const int r = i >> 4, sg = (i & 15) * 4;
            float4 v = *reinterpret_cast<const float4*>(
                g_V + (size_t)(b * L + half * 256 + r) * HID + h * HD + sg);
            float4 rv = make_float4(tf32r(v.x), tf32r(v.y), tf32r(v.z), tf32r(v.w));
            *reinterpret_cast<float4*>(sKV + r * 72 + sg) = rv;
        }
        __syncthreads();

        const float* aS = sS + half * 256;
#pragma unroll
        for (int ks = 0; ks < 32; ks++) {
            const int kb = ks * 8;
            float a[4], bb[2];
            a[0] = aS[(mrw + g    ) * 516 + kb + t];
            a[1] = aS[(mrw + g + 8) * 516 + kb + t];
            a[2] = aS[(mrw + g    ) * 516 + kb + t + 4];
            a[3] = aS[(mrw + g + 8) * 516 + kb + t + 4];
            bb[0] = sKV[(kb + t    ) * 72 + nbw + g];
            bb[1] = sKV[(kb + t + 4) * 72 + nbw + g];
            mma_tf32(acc1, a, bb);
        }
        __syncthreads();
    }

    // ---------- stage 5: bucket scatter + stage table_v ----------
    {
        const int q  = tid >> 4;
        const int kg = tid & 15;
        const unsigned char* fr = sFb + q * 516;
        const float* ar = sS + q * 516;
        float* sbq = sSb + q * 136;
#pragma unroll 4
        for (int i = 0; i < 32; i++) {
            const int k = i * 16 + kg;
            atomicAdd(&sbq[fr[k]], ar[k]);
        }
    }
    for (int i = tid; i < 136 * 16; i += 512) {
        const int r = i >> 4, sg = (i & 15) * 4;
        float4 v = make_float4(0.f, 0.f, 0.f, 0.f);
        if (r < TAB) v = *reinterpret_cast<const float4*>(table_v + r * 64 + sg);
        float4 rv = make_float4(tf32r(v.x), tf32r(v.y), tf32r(v.z), tf32r(v.w));
        *reinterpret_cast<float4*>(sKV + r * 72 + sg) = rv;
    }
    __syncthreads();

    // round buckets to tf32 (rna)
    for (int i = tid; i < 32 * 136; i += 512) sSb[i] = tf32r(sSb[i]);
    __syncthreads();

    // ---------- stage 6: w2 = buckets @ table_v (k padded to 136 -> 17 steps) ----------
    float acc2[4] = {0.f, 0.f, 0.f, 0.f};
#pragma unroll
    for (int ks = 0; ks < 17; ks++) {
        const int kb = ks * 8;
        float a[4], bb[2];
        a[0] = sSb[(mrw + g    ) * 136 + kb + t];
        a[1] = sSb[(mrw + g + 8) * 136 + kb + t];
        a[2] = sSb[(mrw + g    ) * 136 + kb + t + 4];
        a[3] = sSb[(mrw + g + 8) * 136 + kb + t + 4];
        bb[0] = sKV[(kb + t    ) * 72 + nbw + g];
        bb[1] = sKV[(kb + t + 4) * 72 + nbw + g];
        mma_tf32(acc2, a, bb);
    }

    // ---------- store ----------
    {
        const int row0 = mrw + g;
        const int col  = nbw + 2 * t;
        float2 o0 = make_float2(acc1[0] + acc2[0], acc1[1] + acc2[1]);
        float2 o1 = make_float2(acc1[2] + acc2[2], acc1[3] + acc2[3]);
        *reinterpret_cast<float2*>(
            g_X + (size_t)(b * L + q0 + row0) * HID + h * HD + col) = o0;
        *reinterpret_cast<float2*>(
            g_X + (size_t)(b * L + q0 + row0 + 8) * HID + h * HD + col) = o1;
    }
}

// =====================================================================
// launch
// =====================================================================
extern "C" void kernel_launch(void* const* d_in, const int* in_sizes, int n_in,
                              void* d_out, int out_size)
{
    const float* query   = (const float*)d_in[0];
    const float* key     = (const float*)d_in[1];
    const float* value   = (const float*)d_in[2];
    const int*   fm      = (const int*)  d_in[3];
    const float* Wq      = (const float*)d_in[4];
    const float* bq      = (const float*)d_in[5];
    const float* Wk      = (const float*)d_in[6];
    const float* bk      = (const float*)d_in[7];
    const float* Wv      = (const float*)d_in[8];
    const float* bv      = (const float*)d_in[9];
    const float* Wo      = (const float*)d_in[10];
    const float* bo      = (const float*)d_in[11];
    const float* table_k = (const float*)d_in[12];
    const float* table_v = (const float*)d_in[13];
    float* out = (float*)d_out;

    cudaFuncSetAttribute(attn_fused_mma,
                         cudaFuncAttributeMaxDynamicSharedMemorySize, (int)SMF_BYTES);

    float* gQ; cudaGetSymbolAddress((void**)&gQ, g_Q);
    float* gK; cudaGetSymbolAddress((void**)&gK, g_K);
    float* gV; cudaGetSymbolAddress((void**)&gV, g_V);
    float* gX; cudaGetSymbolAddress((void**)&gX, g_X);

    const dim3 gproj(HID / 128, BL / 128);  // (8, 32)
    gemm_tf32<<<gproj, 256>>>(query, Wq, bq, gQ, BL, HID, HID);
    gemm_tf32<<<gproj, 256>>>(key,   Wk, bk, gK, BL, HID, HID);
    gemm_tf32<<<gproj, 256>>>(value, Wv, bv, gV, BL, HID, HID);

    const dim3 gattn(L / 32, H, B);  // (16, 16, 8)
    attn_fused_mma<<<gattn, 512, SMF_BYTES>>>(fm, table_k, table_v);

    gemm_tf32<<<gproj, 256>>>(gX, Wo, bo, out, BL, HID, HID);
}

// round 6
// speedup vs baseline: 3.7119x; 1.1761x over previous
#include <cuda_runtime.h>

// ---------------- problem constants ----------------
constexpr int B    = 8;
constexpr int L    = 512;
constexpr int HID  = 1024;
constexpr int H    = 16;
constexpr int HD   = 64;     // head dim
constexpr int TAB  = 129;    // 2*64+1 relative-position table rows
constexpr int BL   = B * L;  // 4096

// ---------------- device scratch ----------------
__device__ float g_Q[BL * HID];
__device__ float g_K[BL * HID];
__device__ float g_V[BL * HID];
__device__ float g_X[BL * HID];   // w1+w2 merged, [B,L,HID]

// =====================================================================
// tf32 helpers
// =====================================================================
__device__ __forceinline__ float tf32r(float x) {
    unsigned y;
    asm("cvt.rna.tf32.f32 %0, %1;" : "=r"(y) : "f"(x));
    return __uint_as_float(y);
}

__device__ __forceinline__ void mma_tf32(float d[4], const float a[4], const float b[2]) {
    unsigned const* A = reinterpret_cast<unsigned const*>(a);
    unsigned const* Bp = reinterpret_cast<unsigned const*>(b);
    asm volatile(
        "mma.sync.aligned.m16n8k8.row.col.f32.tf32.tf32.f32 "
        "{%0,%1,%2,%3}, {%4,%5,%6,%7}, {%8,%9}, {%0,%1,%2,%3};"
        : "+f"(d[0]), "+f"(d[1]), "+f"(d[2]), "+f"(d[3])
        : "r"(A[0]), "r"(A[1]), "r"(A[2]), "r"(A[3]),
          "r"(Bp[0]), "r"(Bp[1]));
}

// =====================================================================
// Merged Q/K/V projection GEMM: z = 0/1/2 selects (A,W,bias,C).
// C[4096,1024] = A @ W^T + bias. 128x128x32 tile, 256 thr.
// =====================================================================
constexpr int SKS = 36;

__global__ __launch_bounds__(256) void gemm_qkv(
    const float* __restrict__ q_in, const float* __restrict__ k_in,
    const float* __restrict__ v_in,
    const float* __restrict__ Wq, const float* __restrict__ bq,
    const float* __restrict__ Wk, const float* __restrict__ bk,
    const float* __restrict__ Wv, const float* __restrict__ bv)
{
    const float* A; const float* W; const float* bias; float* C;
    if (blockIdx.z == 0)      { A = q_in; W = Wq; bias = bq; C = g_Q; }
    else if (blockIdx.z == 1) { A = k_in; W = Wk; bias = bk; C = g_K; }
    else                      { A = v_in; W = Wv; bias = bv; C = g_V; }

    __shared__ float As[128 * SKS];
    __shared__ float Bs[128 * SKS];

    const int tid  = threadIdx.x;
    const int m0   = blockIdx.y * 128;
    const int n0   = blockIdx.x * 128;
    const int lane = tid & 31;
    const int g    = lane >> 2;
    const int t    = lane & 3;
    const int warp = tid >> 5;
    const int wm   = warp & 1;
    const int wn   = warp >> 1;

    const int lrow = tid >> 1;
    const int lc   = (tid & 1) * 16;
    const float* Ap = A + (size_t)(m0 + lrow) * HID + lc;
    const float* Wp = W + (size_t)(n0 + lrow) * HID + lc;

    float acc[4][4][4];
#pragma unroll
    for (int i = 0; i < 4; i++)
#pragma unroll
        for (int j = 0; j < 4; j++)
#pragma unroll
            for (int r = 0; r < 4; r++) acc[i][j][r] = 0.f;

    float4 ar[4], wr[4];
#pragma unroll
    for (int j = 0; j < 4; j++) {
        ar[j] = *reinterpret_cast<const float4*>(Ap + 4 * j);
        wr[j] = *reinterpret_cast<const float4*>(Wp + 4 * j);
    }

    for (int k0 = 0; k0 < HID; k0 += 32) {
        float* asd = As + lrow * SKS + lc;
        float* bsd = Bs + lrow * SKS + lc;
#pragma unroll
        for (int j = 0; j < 4; j++) {
            float4 av = make_float4(tf32r(ar[j].x), tf32r(ar[j].y), tf32r(ar[j].z), tf32r(ar[j].w));
            float4 wv = make_float4(tf32r(wr[j].x), tf32r(wr[j].y), tf32r(wr[j].z), tf32r(wr[j].w));
            *reinterpret_cast<float4*>(asd + 4 * j) = av;
            *reinterpret_cast<float4*>(bsd + 4 * j) = wv;
        }
        __syncthreads();

        if (k0 + 32 < HID) {
#pragma unroll
            for (int j = 0; j < 4; j++) {
                ar[j] = *reinterpret_cast<const float4*>(Ap + k0 + 32 + 4 * j);
                wr[j] = *reinterpret_cast<const float4*>(Wp + k0 + 32 + 4 * j);
            }
        }

#pragma unroll
        for (int ks = 0; ks < 4; ks++) {
            const int kc = ks * 8 + t;
            float afr[4][4], bfr[4][2];
#pragma unroll
            for (int mt = 0; mt < 4; mt++) {
                const int r = wm * 64 + mt * 16 + g;
                afr[mt][0] = As[(r    ) * SKS + kc];
                afr[mt][1] = As[(r + 8) * SKS + kc];
                afr[mt][2] = As[(r    ) * SKS + kc + 4];
                afr[mt][3] = As[(r + 8) * SKS + kc + 4];
            }
#pragma unroll
            for (int nt = 0; nt < 4; nt++) {
                const int n = wn * 32 + nt * 8 + g;
                bfr[nt][0] = Bs[n * SKS + kc];
                bfr[nt][1] = Bs[n * SKS + kc + 4];
            }
#pragma unroll
            for (int mt = 0; mt < 4; mt++)
#pragma unroll
                for (int nt = 0; nt < 4; nt++)
                    mma_tf32(acc[mt][nt], afr[mt], bfr[nt]);
        }
        __syncthreads();
    }

#pragma unroll
    for (int mt = 0; mt < 4; mt++) {
        const int row0 = m0 + wm * 64 + mt * 16 + g;
#pragma unroll
        for (int nt = 0; nt < 4; nt++) {
            const int col = n0 + wn * 32 + nt * 8 + 2 * t;
            const float b0 = bias[col], b1 = bias[col + 1];
            float* c0 = C + (size_t)row0 * HID + col;
            float* c1 = C + (size_t)(row0 + 8) * HID + col;
            c0[0] = acc[mt][nt][0] + b0; c0[1] = acc[mt][nt][1] + b1;
            c1[0] = acc[mt][nt][2] + b0; c1[1] = acc[mt][nt][3] + b1;
        }
    }
}

// =====================================================================
// Output projection: out = g_X @ Wo^T + bo (generic version kept)
// =====================================================================
__global__ __launch_bounds__(256) void gemm_out(
    const float* __restrict__ W, const float* __restrict__ bias,
    float* __restrict__ C)
{
    __shared__ float As[128 * SKS];
    __shared__ float Bs[128 * SKS];

    const int tid  = threadIdx.x;
    const int m0   = blockIdx.y * 128;
    const int n0   = blockIdx.x * 128;
    const int lane = tid & 31;
    const int g    = lane >> 2;
    const int t    = lane & 3;
    const int warp = tid >> 5;
    const int wm   = warp & 1;
    const int wn   = warp >> 1;

    const int lrow = tid >> 1;
    const int lc   = (tid & 1) * 16;
    const float* Ap = g_X + (size_t)(m0 + lrow) * HID + lc;
    const float* Wp = W + (size_t)(n0 + lrow) * HID + lc;

    float acc[4][4][4];
#pragma unroll
    for (int i = 0; i < 4; i++)
#pragma unroll
        for (int j = 0; j < 4; j++)
#pragma unroll
            for (int r = 0; r < 4; r++) acc[i][j][r] = 0.f;

    float4 ar[4], wr[4];
#pragma unroll
    for (int j = 0; j < 4; j++) {
        ar[j] = *reinterpret_cast<const float4*>(Ap + 4 * j);
        wr[j] = *reinterpret_cast<const float4*>(Wp + 4 * j);
    }

    for (int k0 = 0; k0 < HID; k0 += 32) {
        float* asd = As + lrow * SKS + lc;
        float* bsd = Bs + lrow * SKS + lc;
#pragma unroll
        for (int j = 0; j < 4; j++) {
            float4 av = make_float4(tf32r(ar[j].x), tf32r(ar[j].y), tf32r(ar[j].z), tf32r(ar[j].w));
            float4 wv = make_float4(tf32r(wr[j].x), tf32r(wr[j].y), tf32r(wr[j].z), tf32r(wr[j].w));
            *reinterpret_cast<float4*>(asd + 4 * j) = av;
            *reinterpret_cast<float4*>(bsd + 4 * j) = wv;
        }
        __syncthreads();

        if (k0 + 32 < HID) {
#pragma unroll
            for (int j = 0; j < 4; j++) {
                ar[j] = *reinterpret_cast<const float4*>(Ap + k0 + 32 + 4 * j);
                wr[j] = *reinterpret_cast<const float4*>(Wp + k0 + 32 + 4 * j);
            }
        }

#pragma unroll
        for (int ks = 0; ks < 4; ks++) {
            const int kc = ks * 8 + t;
            float afr[4][4], bfr[4][2];
#pragma unroll
            for (int mt = 0; mt < 4; mt++) {
                const int r = wm * 64 + mt * 16 + g;
                afr[mt][0] = As[(r    ) * SKS + kc];
                afr[mt][1] = As[(r + 8) * SKS + kc];
                afr[mt][2] = As[(r    ) * SKS + kc + 4];
                afr[mt][3] = As[(r + 8) * SKS + kc + 4];
            }
#pragma unroll
            for (int nt = 0; nt < 4; nt++) {
                const int n = wn * 32 + nt * 8 + g;
                bfr[nt][0] = Bs[n * SKS + kc];
                bfr[nt][1] = Bs[n * SKS + kc + 4];
            }
#pragma unroll
            for (int mt = 0; mt < 4; mt++)
#pragma unroll
                for (int nt = 0; nt < 4; nt++)
                    mma_tf32(acc[mt][nt], afr[mt], bfr[nt]);
        }
        __syncthreads();
    }

#pragma unroll
    for (int mt = 0; mt < 4; mt++) {
        const int row0 = m0 + wm * 64 + mt * 16 + g;
#pragma unroll
        for (int nt = 0; nt < 4; nt++) {
            const int col = n0 + wn * 32 + nt * 8 + 2 * t;
            const float b0 = bias[col], b1 = bias[col + 1];
            float* c0 = C + (size_t)row0 * HID + col;
            float* c1 = C + (size_t)(row0 + 8) * HID + col;
            c0[0] = acc[mt][nt][0] + b0; c0[1] = acc[mt][nt][1] + b1;
            c1[0] = acc[mt][nt][2] + b0; c1[1] = acc[mt][nt][3] + b1;
        }
    }
}

// =====================================================================
// Fully fused MMA attention, v2: Q fragments register-cached per warp.
// block = (32 q, h, b), 512 threads, 16 warps.
// warp -> mh = warp>>3 (m-half), wg = warp&7.
//
// SMEM layout (float offsets):
//  sQ  @ 0      [32][68]            (union w/ sSb [32][136] later)
//  sP  @ 2176   [32][132]
//  sKV @ 6400   table_k[136][68] -> K halves [256][68] -> V halves [256][72]
//               -> table_v [136][72]
//  sS  @ 24832  [32][516]  logits / attn
//  sF  @ 41344  [32][516] bytes (final_mat as uchar)
// =====================================================================
constexpr int OFF_P  = 2176;
constexpr int OFF_KV = 6400;
constexpr int OFF_S  = 24832;
constexpr int OFF_F  = 41344;
constexpr int SMF_TOTAL = OFF_F + 4128;
constexpr size_t SMF_BYTES = (size_t)SMF_TOTAL * 4;  // 181,888 B

__global__ __launch_bounds__(512) void attn_fused_mma(
    const int* __restrict__ fm,
    const float* __restrict__ table_k,
    const float* __restrict__ table_v)
{
    extern __shared__ float smem[];
    float* sQ  = smem;                 // [32][68]
    float* sP  = smem + OFF_P;         // [32][132]
    float* sSb = smem;                 // [32][136] union
    float* sKV = smem + OFF_KV;
    float* sS  = smem + OFF_S;         // [32][516]
    unsigned char* sFb = reinterpret_cast<unsigned char*>(smem + OFF_F);

    const int tid  = threadIdx.x;
    const int lane = tid & 31;
    const int warp = tid >> 5;
    const int g    = lane >> 2;
    const int t    = lane & 3;
    const int mh   = warp >> 3;        // 0..1
    const int wg   = warp & 7;         // 0..7
    const int mr   = mh * 16;
    const int q0   = blockIdx.x * 32;
    const int h    = blockIdx.y;
    const int b    = blockIdx.z;

    // ---------- stage 0: stage Q (tf32), table_k (tf32, padded), fm ----------
    {
        const int q = tid >> 4;
        const int dbase = (tid & 15) * 4;
        float4 v = *reinterpret_cast<const float4*>(
            g_Q + (size_t)(b * L + q0 + q) * HID + h * HD + dbase);
        float4 rv = make_float4(tf32r(v.x), tf32r(v.y), tf32r(v.z), tf32r(v.w));
        *reinterpret_cast<float4*>(sQ + q * 68 + dbase) = rv;
    }
    for (int i = tid; i < 136 * 16; i += 512) {
        const int r = i >> 4, sg = (i & 15) * 4;
        float4 v = make_float4(0.f, 0.f, 0.f, 0.f);
        if (r < TAB) v = *reinterpret_cast<const float4*>(table_k + r * 64 + sg);
        float4 rv = make_float4(tf32r(v.x), tf32r(v.y), tf32r(v.z), tf32r(v.w));
        *reinterpret_cast<float4*>(sKV + r * 68 + sg) = rv;
    }
    for (int i = tid; i < 32 * 128; i += 512) {
        const int q = i >> 7;
        const int kq = (i & 127) * 4;
        const int4 v = *reinterpret_cast<const int4*>(
            fm + (size_t)(b * L + q0 + q) * L + kq);
        uchar4 pk = make_uchar4((unsigned char)v.x, (unsigned char)v.y,
                                (unsigned char)v.z, (unsigned char)v.w);
        *reinterpret_cast<uchar4*>(sFb + q * 516 + kq) = pk;
    }
    __syncthreads();

    // ---------- load Q fragments into registers (reused by P + scores) ----------
    float qf[8][4];
#pragma unroll
    for (int ks = 0; ks < 8; ks++) {
        const int kb = ks * 8;
        qf[ks][0] = sQ[(mr + g    ) * 68 + kb + t];
        qf[ks][1] = sQ[(mr + g + 8) * 68 + kb + t];
        qf[ks][2] = sQ[(mr + g    ) * 68 + kb + t + 4];
        qf[ks][3] = sQ[(mr + g + 8) * 68 + kb + t + 4];
    }

    // ---------- stage 1: P[32][129] = Q @ table_k^T ----------
#pragma unroll
    for (int j = 0; j < 3; j++) {
        const int n8 = wg + 8 * j;
        if (n8 > 16) break;
        const int nb = n8 * 8;
        float acc[4] = {0.f, 0.f, 0.f, 0.f};
#pragma unroll
        for (int ks = 0; ks < 8; ks++) {
            const int kb = ks * 8;
            float bb[2];
            bb[0] = sKV[(nb + g) * 68 + kb + t];
            bb[1] = sKV[(nb + g) * 68 + kb + t + 4];
            mma_tf32(acc, qf[ks], bb);
        }
        const int c0 = nb + 2 * t;
        if (c0 < TAB) {
            sP[(mr + g    ) * 132 + c0] = acc[0];
            sP[(mr + g + 8) * 132 + c0] = acc[2];
        }
        if (c0 + 1 < TAB) {
            sP[(mr + g    ) * 132 + c0 + 1] = acc[1];
            sP[(mr + g + 8) * 132 + c0 + 1] = acc[3];
        }
    }
    __syncthreads();

    // ---------- stage 2: scores = Q@K^T + gather(P), K in 2 halves ----------
    for (int half = 0; half < 2; half++) {
        for (int i = tid; i < 256 * 16; i += 512) {
            const int r = i >> 4, sg = (i & 15) * 4;
            float4 v = *reinterpret_cast<const float4*>(
                g_K + (size_t)(b * L + half * 256 + r) * HID + h * HD + sg);
            float4 rv = make_float4(tf32r(v.x), tf32r(v.y), tf32r(v.z), tf32r(v.w));
            *reinterpret_cast<float4*>(sKV + r * 68 + sg) = rv;
        }
        __syncthreads();

        // warp computes 4 n-tiles (n8 = wg*4+j), a-frags from registers
        float acc4[4][4];
#pragma unroll
        for (int j = 0; j < 4; j++)
#pragma unroll
            for (int r = 0; r < 4; r++) acc4[j][r] = 0.f;

#pragma unroll
        for (int ks = 0; ks < 8; ks++) {
            const int kb = ks * 8;
#pragma unroll
            for (int j = 0; j < 4; j++) {
                const int nb = (wg * 4 + j) * 8;
                float bb[2];
                bb[0] = sKV[(nb + g) * 68 + kb + t];
                bb[1] = sKV[(nb + g) * 68 + kb + t + 4];
                mma_tf32(acc4[j], qf[ks], bb);
            }
        }

#pragma unroll
        for (int j = 0; j < 4; j++) {
            const int nb = (wg * 4 + j) * 8;
            const int row0 = mr + g, row1 = row0 + 8;
            const int kc = half * 256 + nb + 2 * t;
            const int t00 = sFb[row0 * 516 + kc], t01 = sFb[row0 * 516 + kc + 1];
            const int t10 = sFb[row1 * 516 + kc], t11 = sFb[row1 * 516 + kc + 1];
            sS[row0 * 516 + kc    ] = (acc4[j][0] + sP[row0 * 132 + t00]) * 0.125f;
            sS[row0 * 516 + kc + 1] = (acc4[j][1] + sP[row0 * 132 + t01]) * 0.125f;
            sS[row1 * 516 + kc    ] = (acc4[j][2] + sP[row1 * 132 + t10]) * 0.125f;
            sS[row1 * 516 + kc + 1] = (acc4[j][3] + sP[row1 * 132 + t11]) * 0.125f;
        }
        __syncthreads();
    }

    // ---------- stage 3: softmax (16 warps x 2 rows) ----------
    for (int r = warp * 2; r < warp * 2 + 2; r++) {
        float* row = sS + r * 516;
        float m = -1e30f;
#pragma unroll
        for (int i = 0; i < 16; i++) m = fmaxf(m, row[lane + 32 * i]);
#pragma unroll
        for (int o = 16; o > 0; o >>= 1) m = fmaxf(m, __shfl_xor_sync(0xffffffffu, m, o));
        float e[16];
        float s = 0.f;
#pragma unroll
        for (int i = 0; i < 16; i++) {
            e[i] = __expf(row[lane + 32 * i] - m);
            s += e[i];
        }
#pragma unroll
        for (int o = 16; o > 0; o >>= 1) s += __shfl_xor_sync(0xffffffffu, s, o);
        const float inv = 1.f / s;
#pragma unroll
        for (int i = 0; i < 16; i++) row[lane + 32 * i] = tf32r(e[i] * inv);
    }
    __syncthreads();

    // zero buckets (sQ/sP dead)
    for (int i = tid; i < 32 * 136; i += 512) sSb[i] = 0.f;

    // ---------- stage 4: w1 = attn @ V (warp tile: rows mr..mr+15, cols wg*8..+7) ----------
    const int nbw = wg * 8;
    float acc1[4] = {0.f, 0.f, 0.f, 0.f};
    for (int half = 0; half < 2; half++) {
        for (int i = tid; i < 256 * 16; i += 512) {
            const int r = i >> 4, sg = (i & 15) * 4;
            float4 v = *reinterpret_cast<const float4*>(
                g_V + (size_t)(b * L + half * 256 + r) * HID + h * HD + sg);
            float4 rv = make_float4(tf32r(v.x), tf32r(v.y), tf32r(v.z), tf32r(v.w));
            *reinterpret_cast<float4*>(sKV + r * 72 + sg) = rv;
        }
        __syncthreads();

        const float* aS = sS + half * 256;
#pragma unroll
        for (int ks = 0; ks < 32; ks++) {
            const int kb = ks * 8;
            float a[4], bb[2];
            a[0] = aS[(mr + g    ) * 516 + kb + t];
            a[1] = aS[(mr + g + 8) * 516 + kb + t];
            a[2] = aS[(mr + g    ) * 516 + kb + t + 4];
            a[3] = aS[(mr + g + 8) * 516 + kb + t + 4];
            bb[0] = sKV[(kb + t    ) * 72 + nbw + g];
            bb[1] = sKV[(kb + t + 4) * 72 + nbw + g];
            mma_tf32(acc1, a, bb);
        }
        __syncthreads();
    }

    // ---------- stage 5: bucket scatter + stage table_v ----------
    {
        const int q  = tid >> 4;
        const int kg = tid & 15;
        const unsigned char* fr = sFb + q * 516;
        const float* ar = sS + q * 516;
        float* sbq = sSb + q * 136;
#pragma unroll 4
        for (int i = 0; i < 32; i++) {
            const int k = i * 16 + kg;
            atomicAdd(&sbq[fr[k]], ar[k]);
        }
    }
    for (int i = tid; i < 136 * 16; i += 512) {
        const int r = i >> 4, sg = (i & 15) * 4;
        float4 v = make_float4(0.f, 0.f, 0.f, 0.f);
        if (r < TAB) v = *reinterpret_cast<const float4*>(table_v + r * 64 + sg);
        float4 rv = make_float4(tf32r(v.x), tf32r(v.y), tf32r(v.z), tf32r(v.w));
        *reinterpret_cast<float4*>(sKV + r * 72 + sg) = rv;
    }
    __syncthreads();

    // round buckets to tf32
    for (int i = tid; i < 32 * 136; i += 512) sSb[i] = tf32r(sSb[i]);
    __syncthreads();

    // ---------- stage 6: w2 = buckets @ table_v (17 k-steps) ----------
    float acc2[4] = {0.f, 0.f, 0.f, 0.f};
#pragma unroll
    for (int ks = 0; ks < 17; ks++) {
        const int kb = ks * 8;
        float a[4], bb[2];
        a[0] = sSb[(mr + g    ) * 136 + kb + t];
        a[1] = sSb[(mr + g + 8) * 136 + kb + t];
        a[2] = sSb[(mr + g    ) * 136 + kb + t + 4];
        a[3] = sSb[(mr + g + 8) * 136 + kb + t + 4];
        bb[0] = sKV[(kb + t    ) * 72 + nbw + g];
        bb[1] = sKV[(kb + t + 4) * 72 + nbw + g];
        mma_tf32(acc2, a, bb);
    }

    // ---------- store ----------
    {
        const int row0 = mr + g;
        const int col  = nbw + 2 * t;
        float2 o0 = make_float2(acc1[0] + acc2[0], acc1[1] + acc2[1]);
        float2 o1 = make_float2(acc1[2] + acc2[2], acc1[3] + acc2[3]);
        *reinterpret_cast<float2*>(
            g_X + (size_t)(b * L + q0 + row0) * HID + h * HD + col) = o0;
        *reinterpret_cast<float2*>(
            g_X + (size_t)(b * L + q0 + row0 + 8) * HID + h * HD + col) = o1;
    }
}

// =====================================================================
// launch
// =====================================================================
extern "C" void kernel_launch(void* const* d_in, const int* in_sizes, int n_in,
                              void* d_out, int out_size)
{
    const float* query   = (const float*)d_in[0];
    const float* key     = (const float*)d_in[1];
    const float* value   = (const float*)d_in[2];
    const int*   fm      = (const int*)  d_in[3];
    const float* Wq      = (const float*)d_in[4];
    const float* bq      = (const float*)d_in[5];
    const float* Wk      = (const float*)d_in[6];
    const float* bk      = (const float*)d_in[7];
    const float* Wv      = (const float*)d_in[8];
    const float* bv      = (const float*)d_in[9];
    const float* Wo      = (const float*)d_in[10];
    const float* bo      = (const float*)d_in[11];
    const float* table_k = (const float*)d_in[12];
    const float* table_v = (const float*)d_in[13];
    float* out = (float*)d_out;

    cudaFuncSetAttribute(attn_fused_mma,
                         cudaFuncAttributeMaxDynamicSharedMemorySize, (int)SMF_BYTES);

    const dim3 gqkv(HID / 128, BL / 128, 3);  // (8, 32, 3)
    gemm_qkv<<<gqkv, 256>>>(query, key, value, Wq, bq, Wk, bk, Wv, bv);

    const dim3 gattn(L / 32, H, B);  // (16, 16, 8)
    attn_fused_mma<<<gattn, 512, SMF_BYTES>>>(fm, table_k, table_v);

    const dim3 gout(HID / 128, BL / 128);  // (8, 32)
    gemm_out<<<gout, 256>>>(Wo, bo, out);
}

// round 7
// speedup vs baseline: 4.0236x; 1.0840x over previous
#include <cuda_runtime.h>

// ---------------- problem constants ----------------
constexpr int B    = 8;
constexpr int L    = 512;
constexpr int HID  = 1024;
constexpr int H    = 16;
constexpr int HD   = 64;     // head dim
constexpr int TAB  = 129;    // 2*64+1 relative-position table rows
constexpr int BL   = B * L;  // 4096

// ---------------- device scratch ----------------
__device__ float g_Q[BL * HID];
__device__ float g_K[BL * HID];
__device__ float g_V[BL * HID];
__device__ float g_X[BL * HID];   // w1+w2 merged, [B,L,HID]

// =====================================================================
// tf32 helpers
// =====================================================================
__device__ __forceinline__ float tf32r(float x) {
    unsigned y;
    asm("cvt.rna.tf32.f32 %0, %1;" : "=r"(y) : "f"(x));
    return __uint_as_float(y);
}

__device__ __forceinline__ void mma_tf32(float d[4], const float a[4], const float b[2]) {
    unsigned const* A = reinterpret_cast<unsigned const*>(a);
    unsigned const* Bp = reinterpret_cast<unsigned const*>(b);
    asm volatile(
        "mma.sync.aligned.m16n8k8.row.col.f32.tf32.tf32.f32 "
        "{%0,%1,%2,%3}, {%4,%5,%6,%7}, {%8,%9}, {%0,%1,%2,%3};"
        : "+f"(d[0]), "+f"(d[1]), "+f"(d[2]), "+f"(d[3])
        : "r"(A[0]), "r"(A[1]), "r"(A[2]), "r"(A[3]),
          "r"(Bp[0]), "r"(Bp[1]));
}

// =====================================================================
// Double-buffered tf32 GEMM body (dynamic smem: 2 x (As+Bs) of 128x36)
// C[4096,1024] = A @ W^T + bias
// =====================================================================
constexpr int SKS = 36;
constexpr int GEMM_BUF = 128 * SKS;                 // floats per tile buffer
constexpr size_t GEMM_SMEM = (size_t)4 * GEMM_BUF * 4;  // 73728 B

__device__ __forceinline__ void gemm_body(
    const float* __restrict__ A, const float* __restrict__ W,
    const float* __restrict__ bias, float* __restrict__ C)
{
    extern __shared__ float dsm[];
    float* AsBase = dsm;                 // [2][128*SKS]
    float* BsBase = dsm + 2 * GEMM_BUF;  // [2][128*SKS]

    const int tid  = threadIdx.x;
    const int m0   = blockIdx.y * 128;
    const int n0   = blockIdx.x * 128;
    const int lane = tid & 31;
    const int g    = lane >> 2;
    const int t    = lane & 3;
    const int warp = tid >> 5;
    const int wm   = warp & 1;
    const int wn   = warp >> 1;

    const int lrow = tid >> 1;
    const int lc   = (tid & 1) * 16;
    const float* Ap = A + (size_t)(m0 + lrow) * HID + lc;
    const float* Wp = W + (size_t)(n0 + lrow) * HID + lc;

    float acc[4][4][4];
#pragma unroll
    for (int i = 0; i < 4; i++)
#pragma unroll
        for (int j = 0; j < 4; j++)
#pragma unroll
            for (int r = 0; r < 4; r++) acc[i][j][r] = 0.f;

    float4 ar[4], wr[4];
#pragma unroll
    for (int j = 0; j < 4; j++) {
        ar[j] = *reinterpret_cast<const float4*>(Ap + 4 * j);
        wr[j] = *reinterpret_cast<const float4*>(Wp + 4 * j);
    }
    // prologue: stage tile 0 into buffer 0
    {
        float* asd = AsBase + lrow * SKS + lc;
        float* bsd = BsBase + lrow * SKS + lc;
#pragma unroll
        for (int j = 0; j < 4; j++) {
            float4 av = make_float4(tf32r(ar[j].x), tf32r(ar[j].y), tf32r(ar[j].z), tf32r(ar[j].w));
            float4 wv = make_float4(tf32r(wr[j].x), tf32r(wr[j].y), tf32r(wr[j].z), tf32r(wr[j].w));
            *reinterpret_cast<float4*>(asd + 4 * j) = av;
            *reinterpret_cast<float4*>(bsd + 4 * j) = wv;
        }
    }

    int buf = 0;
    for (int k0 = 0; k0 < HID; k0 += 32, buf ^= 1) {
        __syncthreads();   // buffer `buf` ready; buffer buf^1 free

        const bool more = (k0 + 32 < HID);
        if (more) {
#pragma unroll
            for (int j = 0; j < 4; j++) {
                ar[j] = *reinterpret_cast<const float4*>(Ap + k0 + 32 + 4 * j);
                wr[j] = *reinterpret_cast<const float4*>(Wp + k0 + 32 + 4 * j);
            }
        }

        const float* As = AsBase + buf * GEMM_BUF;
        const float* Bs = BsBase + buf * GEMM_BUF;
#pragma unroll
        for (int ks = 0; ks < 4; ks++) {
            const int kc = ks * 8 + t;
            float afr[4][4], bfr[4][2];
#pragma unroll
            for (int mt = 0; mt < 4; mt++) {
                const int r = wm * 64 + mt * 16 + g;
                afr[mt][0] = As[(r    ) * SKS + kc];
                afr[mt][1] = As[(r + 8) * SKS + kc];
                afr[mt][2] = As[(r    ) * SKS + kc + 4];
                afr[mt][3] = As[(r + 8) * SKS + kc + 4];
            }
#pragma unroll
            for (int nt = 0; nt < 4; nt++) {
                const int n = wn * 32 + nt * 8 + g;
                bfr[nt][0] = Bs[n * SKS + kc];
                bfr[nt][1] = Bs[n * SKS + kc + 4];
            }
#pragma unroll
            for (int mt = 0; mt < 4; mt++)
#pragma unroll
                for (int nt = 0; nt < 4; nt++)
                    mma_tf32(acc[mt][nt], afr[mt], bfr[nt]);
        }

        if (more) {
            float* asd = AsBase + (buf ^ 1) * GEMM_BUF + lrow * SKS + lc;
            float* bsd = BsBase + (buf ^ 1) * GEMM_BUF + lrow * SKS + lc;
#pragma unroll
            for (int j = 0; j < 4; j++) {
                float4 av = make_float4(tf32r(ar[j].x), tf32r(ar[j].y), tf32r(ar[j].z), tf32r(ar[j].w));
                float4 wv = make_float4(tf32r(wr[j].x), tf32r(wr[j].y), tf32r(wr[j].z), tf32r(wr[j].w));
                *reinterpret_cast<float4*>(asd + 4 * j) = av;
                *reinterpret_cast<float4*>(bsd + 4 * j) = wv;
            }
        }
    }

#pragma unroll
    for (int mt = 0; mt < 4; mt++) {
        const int row0 = m0 + wm * 64 + mt * 16 + g;
#pragma unroll
        for (int nt = 0; nt < 4; nt++) {
            const int col = n0 + wn * 32 + nt * 8 + 2 * t;
            const float b0 = bias[col], b1 = bias[col + 1];
            float* c0 = C + (size_t)row0 * HID + col;
            float* c1 = C + (size_t)(row0 + 8) * HID + col;
            c0[0] = acc[mt][nt][0] + b0; c0[1] = acc[mt][nt][1] + b1;
            c1[0] = acc[mt][nt][2] + b0; c1[1] = acc[mt][nt][3] + b1;
        }
    }
}

__global__ __launch_bounds__(256, 2) void gemm_qkv(
    const float* __restrict__ q_in, const float* __restrict__ k_in,
    const float* __restrict__ v_in,
    const float* __restrict__ Wq, const float* __restrict__ bq,
    const float* __restrict__ Wk, const float* __restrict__ bk,
    const float* __restrict__ Wv, const float* __restrict__ bv)
{
    if (blockIdx.z == 0)      gemm_body(q_in, Wq, bq, g_Q);
    else if (blockIdx.z == 1) gemm_body(k_in, Wk, bk, g_K);
    else                      gemm_body(v_in, Wv, bv, g_V);
}

__global__ __launch_bounds__(256, 2) void gemm_out(
    const float* __restrict__ W, const float* __restrict__ bias,
    float* __restrict__ C)
{
    gemm_body(g_X, W, bias, C);
}

// =====================================================================
// Fully fused MMA attention, v3: Q frags in regs + K/V register prefetch
// pipelined across stages. block = (32 q, h, b), 512 threads, 16 warps.
//
// SMEM layout (float offsets):
//  sQ  @ 0      [32][68]            (union w/ sSb [32][136] later)
//  sP  @ 2176   [32][132]
//  sKV @ 6400   table_k[136][68] -> K halves [256][68] -> V halves [256][72]
//               -> table_v [136][72]
//  sS  @ 24832  [32][516]  logits / attn
//  sF  @ 41344  [32][516] bytes (final_mat as uchar)
// =====================================================================
constexpr int OFF_P  = 2176;
constexpr int OFF_KV = 6400;
constexpr int OFF_S  = 24832;
constexpr int OFF_F  = 41344;
constexpr int SMF_TOTAL = OFF_F + 4128;
constexpr size_t SMF_BYTES = (size_t)SMF_TOTAL * 4;  // 181,888 B

__global__ __launch_bounds__(512) void attn_fused_mma(
    const int* __restrict__ fm,
    const float* __restrict__ table_k,
    const float* __restrict__ table_v)
{
    extern __shared__ float smem[];
    float* sQ  = smem;                 // [32][68]
    float* sP  = smem + OFF_P;         // [32][132]
    float* sSb = smem;                 // [32][136] union
    float* sKV = smem + OFF_KV;
    float* sS  = smem + OFF_S;         // [32][516]
    unsigned char* sFb = reinterpret_cast<unsigned char*>(smem + OFF_F);

    const int tid  = threadIdx.x;
    const int lane = tid & 31;
    const int warp = tid >> 5;
    const int g    = lane >> 2;
    const int t    = lane & 3;
    const int mh   = warp >> 3;        // 0..1
    const int wg   = warp & 7;         // 0..7
    const int mr   = mh * 16;
    const int q0   = blockIdx.x * 32;
    const int h    = blockIdx.y;
    const int b    = blockIdx.z;

    // prefetch-index mapping (8 float4 per thread covers a 256-row half)
    const int pr  = tid >> 4;          // base row 0..31 (advances by 32)
    const int psg = (tid & 15) * 4;    // float offset in row
    const float* gKb = g_K + (size_t)(b * L) * HID + h * HD;
    const float* gVb = g_V + (size_t)(b * L) * HID + h * HD;

    // ---------- stage 0: stage Q (tf32), table_k (tf32, padded), fm ----------
    {
        const int q = tid >> 4;
        const int dbase = (tid & 15) * 4;
        float4 v = *reinterpret_cast<const float4*>(
            g_Q + (size_t)(b * L + q0 + q) * HID + h * HD + dbase);
        float4 rv = make_float4(tf32r(v.x), tf32r(v.y), tf32r(v.z), tf32r(v.w));
        *reinterpret_cast<float4*>(sQ + q * 68 + dbase) = rv;
    }
    for (int i = tid; i < 136 * 16; i += 512) {
        const int r = i >> 4, sg = (i & 15) * 4;
        float4 v = make_float4(0.f, 0.f, 0.f, 0.f);
        if (r < TAB) v = *reinterpret_cast<const float4*>(table_k + r * 64 + sg);
        float4 rv = make_float4(tf32r(v.x), tf32r(v.y), tf32r(v.z), tf32r(v.w));
        *reinterpret_cast<float4*>(sKV + r * 68 + sg) = rv;
    }
    for (int i = tid; i < 32 * 128; i += 512) {
        const int q = i >> 7;
        const int kq = (i & 127) * 4;
        const int4 v = *reinterpret_cast<const int4*>(
            fm + (size_t)(b * L + q0 + q) * L + kq);
        uchar4 pk = make_uchar4((unsigned char)v.x, (unsigned char)v.y,
                                (unsigned char)v.z, (unsigned char)v.w);
        *reinterpret_cast<uchar4*>(sFb + q * 516 + kq) = pk;
    }

    // issue K half-0 global loads now (consumed after P stage)
    float4 pf[8];
#pragma unroll
    for (int j = 0; j < 8; j++)
        pf[j] = *reinterpret_cast<const float4*>(
            gKb + (size_t)(pr + 32 * j) * HID + psg);

    __syncthreads();

    // ---------- Q fragments into registers ----------
    float qf[8][4];
#pragma unroll
    for (int ks = 0; ks < 8; ks++) {
        const int kb = ks * 8;
        qf[ks][0] = sQ[(mr + g    ) * 68 + kb + t];
        qf[ks][1] = sQ[(mr + g + 8) * 68 + kb + t];
        qf[ks][2] = sQ[(mr + g    ) * 68 + kb + t + 4];
        qf[ks][3] = sQ[(mr + g + 8) * 68 + kb + t + 4];
    }

    // ---------- stage 1: P[32][129] = Q @ table_k^T ----------
#pragma unroll
    for (int j = 0; j < 3; j++) {
        const int n8 = wg + 8 * j;
        if (n8 > 16) break;
        const int nb = n8 * 8;
        float acc[4] = {0.f, 0.f, 0.f, 0.f};
#pragma unroll
        for (int ks = 0; ks < 8; ks++) {
            const int kb = ks * 8;
            float bb[2];
            bb[0] = sKV[(nb + g) * 68 + kb + t];
            bb[1] = sKV[(nb + g) * 68 + kb + t + 4];
            mma_tf32(acc, qf[ks], bb);
        }
        const int c0 = nb + 2 * t;
        if (c0 < TAB) {
            sP[(mr + g    ) * 132 + c0] = acc[0];
            sP[(mr + g + 8) * 132 + c0] = acc[2];
        }
        if (c0 + 1 < TAB) {
            sP[(mr + g    ) * 132 + c0 + 1] = acc[1];
            sP[(mr + g + 8) * 132 + c0 + 1] = acc[3];
        }
    }
    __syncthreads();   // table_k region dead

    // ---------- scores: half 0 ----------
    // store prefetched K0, issue K1 loads
#pragma unroll
    for (int j = 0; j < 8; j++) {
        float4 rv = make_float4(tf32r(pf[j].x), tf32r(pf[j].y), tf32r(pf[j].z), tf32r(pf[j].w));
        *reinterpret_cast<float4*>(sKV + (pr + 32 * j) * 68 + psg) = rv;
    }
#pragma unroll
    for (int j = 0; j < 8; j++)
        pf[j] = *reinterpret_cast<const float4*>(
            gKb + (size_t)(256 + pr + 32 * j) * HID + psg);
    __syncthreads();

#pragma unroll
    for (int half = 0; half < 2; half++) {
        float acc4[4][4];
#pragma unroll
        for (int j = 0; j < 4; j++)
#pragma unroll
            for (int r = 0; r < 4; r++) acc4[j][r] = 0.f;

#pragma unroll
        for (int ks = 0; ks < 8; ks++) {
            const int kb = ks * 8;
#pragma unroll
            for (int j = 0; j < 4; j++) {
                const int nb = (wg * 4 + j) * 8;
                float bb[2];
                bb[0] = sKV[(nb + g) * 68 + kb + t];
                bb[1] = sKV[(nb + g) * 68 + kb + t + 4];
                mma_tf32(acc4[j], qf[ks], bb);
            }
        }

#pragma unroll
        for (int j = 0; j < 4; j++) {
            const int nb = (wg * 4 + j) * 8;
            const int row0 = mr + g, row1 = row0 + 8;
            const int kc = half * 256 + nb + 2 * t;
            const int t00 = sFb[row0 * 516 + kc], t01 = sFb[row0 * 516 + kc + 1];
            const int t10 = sFb[row1 * 516 + kc], t11 = sFb[row1 * 516 + kc + 1];
            sS[row0 * 516 + kc    ] = (acc4[j][0] + sP[row0 * 132 + t00]) * 0.125f;
            sS[row0 * 516 + kc + 1] = (acc4[j][1] + sP[row0 * 132 + t01]) * 0.125f;
            sS[row1 * 516 + kc    ] = (acc4[j][2] + sP[row1 * 132 + t10]) * 0.125f;
            sS[row1 * 516 + kc + 1] = (acc4[j][3] + sP[row1 * 132 + t11]) * 0.125f;
        }
        __syncthreads();

        if (half == 0) {
            // store K1, issue V0 loads
#pragma unroll
            for (int j = 0; j < 8; j++) {
                float4 rv = make_float4(tf32r(pf[j].x), tf32r(pf[j].y), tf32r(pf[j].z), tf32r(pf[j].w));
                *reinterpret_cast<float4*>(sKV + (pr + 32 * j) * 68 + psg) = rv;
            }
#pragma unroll
            for (int j = 0; j < 8; j++)
                pf[j] = *reinterpret_cast<const float4*>(
                    gVb + (size_t)(pr + 32 * j) * HID + psg);
            __syncthreads();
        }
    }

    // ---------- softmax (16 warps x 2 rows) + zero buckets ----------
    for (int r = warp * 2; r < warp * 2 + 2; r++) {
        float* row = sS + r * 516;
        float m = -1e30f;
#pragma unroll
        for (int i = 0; i < 16; i++) m = fmaxf(m, row[lane + 32 * i]);
#pragma unroll
        for (int o = 16; o > 0; o >>= 1) m = fmaxf(m, __shfl_xor_sync(0xffffffffu, m, o));
        float e[16];
        float s = 0.f;
#pragma unroll
        for (int i = 0; i < 16; i++) {
            e[i] = __expf(row[lane + 32 * i] - m);
            s += e[i];
        }
#pragma unroll
        for (int o = 16; o > 0; o >>= 1) s += __shfl_xor_sync(0xffffffffu, s, o);
        const float inv = 1.f / s;
#pragma unroll
        for (int i = 0; i < 16; i++) row[lane + 32 * i] = tf32r(e[i] * inv);
    }
    for (int i = tid; i < 32 * 136; i += 512) sSb[i] = 0.f;
    __syncthreads();

    // ---------- w1 = attn @ V with V prefetch pipeline ----------
    const int nbw = wg * 8;
    float acc1[4] = {0.f, 0.f, 0.f, 0.f};
#pragma unroll
    for (int half = 0; half < 2; half++) {
        // store prefetched V half; on half 0, issue V1 loads
#pragma unroll
        for (int j = 0; j < 8; j++) {
            float4 rv = make_float4(tf32r(pf[j].x), tf32r(pf[j].y), tf32r(pf[j].z), tf32r(pf[j].w));
            *reinterpret_cast<float4*>(sKV + (pr + 32 * j) * 72 + psg) = rv;
        }
        if (half == 0) {
#pragma unroll
            for (int j = 0; j < 8; j++)
                pf[j] = *reinterpret_cast<const float4*>(
                    gVb + (size_t)(256 + pr + 32 * j) * HID + psg);
        }
        __syncthreads();

        const float* aS = sS + half * 256;
#pragma unroll
        for (int ks = 0; ks < 32; ks++) {
            const int kb = ks * 8;
            float a[4], bb[2];
            a[0] = aS[(mr + g    ) * 516 + kb + t];
            a[1] = aS[(mr + g + 8) * 516 + kb + t];
            a[2] = aS[(mr + g    ) * 516 + kb + t + 4];
            a[3] = aS[(mr + g + 8) * 516 + kb + t + 4];
            bb[0] = sKV[(kb + t    ) * 72 + nbw + g];
            bb[1] = sKV[(kb + t + 4) * 72 + nbw + g];
            mma_tf32(acc1, a, bb);
        }
        __syncthreads();
    }

    // ---------- bucket scatter + stage table_v ----------
    {
        const int q  = tid >> 4;
        const int kg = tid & 15;
        const unsigned char* fr = sFb + q * 516;
        const float* ar = sS + q * 516;
        float* sbq = sSb + q * 136;
#pragma unroll 4
        for (int i = 0; i < 32; i++) {
            const int k = i * 16 + kg;
            atomicAdd(&sbq[fr[k]], ar[k]);
        }
    }
    for (int i = tid; i < 136 * 16; i += 512) {
        const int r = i >> 4, sg = (i & 15) * 4;
        float4 v = make_float4(0.f, 0.f, 0.f, 0.f);
        if (r < TAB) v = *reinterpret_cast<const float4*>(table_v + r * 64 + sg);
        float4 rv = make_float4(tf32r(v.x), tf32r(v.y), tf32r(v.z), tf32r(v.w));
        *reinterpret_cast<float4*>(sKV + r * 72 + sg) = rv;
    }
    __syncthreads();

    // ---------- w2 = buckets @ table_v (tf32-round folded into frag loads) ----------
    float acc2[4] = {0.f, 0.f, 0.f, 0.f};
#pragma unroll
    for (int ks = 0; ks < 17; ks++) {
        const int kb = ks * 8;
        float a[4], bb[2];
        a[0] = tf32r(sSb[(mr + g    ) * 136 + kb + t]);
        a[1] = tf32r(sSb[(mr + g + 8) * 136 + kb + t]);
        a[2] = tf32r(sSb[(mr + g    ) * 136 + kb + t + 4]);
        a[3] = tf32r(sSb[(mr + g + 8) * 136 + kb + t + 4]);
        bb[0] = sKV[(kb + t    ) * 72 + nbw + g];
        bb[1] = sKV[(kb + t + 4) * 72 + nbw + g];
        mma_tf32(acc2, a, bb);
    }

    // ---------- store ----------
    {
        const int row0 = mr + g;
        const int col  = nbw + 2 * t;
        float2 o0 = make_float2(acc1[0] + acc2[0], acc1[1] + acc2[1]);
        float2 o1 = make_float2(acc1[2] + acc2[2], acc1[3] + acc2[3]);
        *reinterpret_cast<float2*>(
            g_X + (size_t)(b * L + q0 + row0) * HID + h * HD + col) = o0;
        *reinterpret_cast<float2*>(
            g_X + (size_t)(b * L + q0 + row0 + 8) * HID + h * HD + col) = o1;
    }
}

// =====================================================================
// launch
// =====================================================================
extern "C" void kernel_launch(void* const* d_in, const int* in_sizes, int n_in,
                              void* d_out, int out_size)
{
    const float* query   = (const float*)d_in[0];
    const float* key     = (const float*)d_in[1];
    const float* value   = (const float*)d_in[2];
    const int*   fm      = (const int*)  d_in[3];
    const float* Wq      = (const float*)d_in[4];
    const float* bq      = (const float*)d_in[5];
    const float* Wk      = (const float*)d_in[6];
    const float* bk      = (const float*)d_in[7];
    const float* Wv      = (const float*)d_in[8];
    const float* bv      = (const float*)d_in[9];
    const float* Wo      = (const float*)d_in[10];
    const float* bo      = (const float*)d_in[11];
    const float* table_k = (const float*)d_in[12];
    const float* table_v = (const float*)d_in[13];
    float* out = (float*)d_out;

    cudaFuncSetAttribute(attn_fused_mma,
                         cudaFuncAttributeMaxDynamicSharedMemorySize, (int)SMF_BYTES);
    cudaFuncSetAttribute(gemm_qkv,
                         cudaFuncAttributeMaxDynamicSharedMemorySize, (int)GEMM_SMEM);
    cudaFuncSetAttribute(gemm_out,
                         cudaFuncAttributeMaxDynamicSharedMemorySize, (int)GEMM_SMEM);

    const dim3 gqkv(HID / 128, BL / 128, 3);  // (8, 32, 3)
    gemm_qkv<<<gqkv, 256, GEMM_SMEM>>>(query, key, value, Wq, bq, Wk, bk, Wv, bv);

    const dim3 gattn(L / 32, H, B);  // (16, 16, 8)
    attn_fused_mma<<<gattn, 512, SMF_BYTES>>>(fm, table_k, table_v);

    const dim3 gout(HID / 128, BL / 128);  // (8, 32)
    gemm_out<<<gout, 256, GEMM_SMEM>>>(Wo, bo, out);
}